// round 1
// baseline (speedup 1.0000x reference)
#include <cuda_runtime.h>
#include <cuda_bf16.h>
#include <math.h>

#define NN   50000
#define EE   800000
#define DIN_ 500
#define HH   128
#define CC   40
#define BB   10000
#define LL   9
#define KK   5
#define ALPHA 0.5f
#define ETA   0.5f

// ------------------------- scratch (device globals) -------------------------
__device__ float g_h[NN * HH];
__device__ float g_x0[NN * HH];
__device__ float g_p[NN * HH];
__device__ int   g_cnt[NN];
__device__ int   g_fill[NN];
__device__ int   g_rowptr[NN + 1];
__device__ int   g_colidx[EE];
__device__ float g_wsorted[EE];
__device__ float g_an[BB * HH];
__device__ float g_plc[BB * CC];
__device__ float g_topv[BB * KK];
__device__ int   g_topi[BB * KK];

// ------------------------- small helpers -------------------------
__device__ __forceinline__ float warp_max(float v) {
    #pragma unroll
    for (int o = 16; o > 0; o >>= 1) v = fmaxf(v, __shfl_xor_sync(0xffffffffu, v, o));
    return v;
}
__device__ __forceinline__ float warp_sum(float v) {
    #pragma unroll
    for (int o = 16; o > 0; o >>= 1) v += __shfl_xor_sync(0xffffffffu, v, o);
    return v;
}

// top-5 insertion, sorted descending; ties -> lower index first (jax top_k)
__device__ __forceinline__ void topk_insert(float (&tv)[KK], int (&ti)[KK], float v, int c) {
    if (v > tv[KK - 1] || (v == tv[KK - 1] && c < ti[KK - 1])) {
        tv[KK - 1] = v; ti[KK - 1] = c;
        #pragma unroll
        for (int p = KK - 1; p > 0; p--) {
            bool sw = (tv[p] > tv[p - 1]) || (tv[p] == tv[p - 1] && ti[p] < ti[p - 1]);
            if (sw) {
                float fv = tv[p]; tv[p] = tv[p - 1]; tv[p - 1] = fv;
                int fi = ti[p]; ti[p] = ti[p - 1]; ti[p - 1] = fi;
            }
        }
    }
}

// ------------------------- CSR build -------------------------
__global__ void zero_counts_kernel() {
    int i = blockIdx.x * blockDim.x + threadIdx.x;
    if (i < NN) { g_cnt[i] = 0; g_fill[i] = 0; }
}

__global__ void hist_kernel(const int* __restrict__ ei) {
    int e = blockIdx.x * blockDim.x + threadIdx.x;
    if (e < EE) atomicAdd(&g_cnt[ei[e]], 1);
}

__global__ void scan_kernel() {
    __shared__ int sh[1024];
    int carry = 0;
    if (threadIdx.x == 0) g_rowptr[0] = 0;
    for (int base = 0; base < NN; base += 1024) {
        int i = base + threadIdx.x;
        int v = (i < NN) ? g_cnt[i] : 0;
        sh[threadIdx.x] = v;
        __syncthreads();
        #pragma unroll
        for (int off = 1; off < 1024; off <<= 1) {
            int t = 0;
            if (threadIdx.x >= off) t = sh[threadIdx.x - off];
            __syncthreads();
            sh[threadIdx.x] += t;
            __syncthreads();
        }
        if (i < NN) g_rowptr[i + 1] = carry + sh[threadIdx.x];
        carry += sh[1023];
        __syncthreads();
    }
}

__global__ void csr_fill_kernel(const int* __restrict__ ei, const float* __restrict__ ew) {
    int e = blockIdx.x * blockDim.x + threadIdx.x;
    if (e < EE) {
        int r = ei[e];
        int pos = g_rowptr[r] + atomicAdd(&g_fill[r], 1);
        g_colidx[pos] = ei[EE + e];
        g_wsorted[pos] = ew[e];
    }
}

// ------------------------- input GEMM: h = relu(x@W1 + b1), x0 = h -------------------------
// block: 256 threads, tile 64 rows x 128 cols, BK=20 (500 = 25*20)
#define IG_BK 20
__global__ __launch_bounds__(256) void input_gemm_kernel(const float* __restrict__ x,
                                                         const float* __restrict__ W1,
                                                         const float* __restrict__ b1) {
    __shared__ float As[64][IG_BK + 1];
    __shared__ float Ws[IG_BK][HH];
    int tid = threadIdx.x;
    int tc = tid & 31;   // 32 col groups of 4
    int tr = tid >> 5;   // 8 row groups of 8
    int row0 = blockIdx.x * 64;

    float acc[8][4];
    #pragma unroll
    for (int i = 0; i < 8; i++)
        #pragma unroll
        for (int j = 0; j < 4; j++) acc[i][j] = 0.f;

    for (int k0 = 0; k0 < DIN_; k0 += IG_BK) {
        #pragma unroll
        for (int t = 0; t < 5; t++) {
            int f = tid + t * 256;           // < 1280
            int r = f / IG_BK, k = f % IG_BK;
            int gr = row0 + r;
            As[r][k] = (gr < NN) ? x[gr * DIN_ + k0 + k] : 0.f;
        }
        #pragma unroll
        for (int t = 0; t < 10; t++) {
            int f = tid + t * 256;           // < 2560
            int k = f / HH, c = f % HH;
            Ws[k][c] = W1[(k0 + k) * HH + c];
        }
        __syncthreads();
        #pragma unroll
        for (int k = 0; k < IG_BK; k++) {
            float4 b = *(const float4*)&Ws[k][tc * 4];
            #pragma unroll
            for (int i = 0; i < 8; i++) {
                float a = As[tr * 8 + i][k];
                acc[i][0] += a * b.x; acc[i][1] += a * b.y;
                acc[i][2] += a * b.z; acc[i][3] += a * b.w;
            }
        }
        __syncthreads();
    }
    float4 bias = *(const float4*)&b1[tc * 4];
    #pragma unroll
    for (int i = 0; i < 8; i++) {
        int gr = row0 + tr * 8 + i;
        if (gr < NN) {
            float4 v;
            v.x = fmaxf(acc[i][0] + bias.x, 0.f);
            v.y = fmaxf(acc[i][1] + bias.y, 0.f);
            v.z = fmaxf(acc[i][2] + bias.z, 0.f);
            v.w = fmaxf(acc[i][3] + bias.w, 0.f);
            *(float4*)&g_h[gr * HH + tc * 4] = v;
            *(float4*)&g_x0[gr * HH + tc * 4] = v;
        }
    }
}

// ------------------------- SpMM: p = (1-alpha) * A @ h (CSR, warp per row) ----------------
__global__ __launch_bounds__(256) void spmm_kernel() {
    int gt = blockIdx.x * blockDim.x + threadIdx.x;
    int row = gt >> 5;
    int lane = gt & 31;
    if (row >= NN) return;
    int s = g_rowptr[row], e = g_rowptr[row + 1];
    float4 acc = make_float4(0.f, 0.f, 0.f, 0.f);
    for (int i = s; i < e; i++) {
        int c = g_colidx[i];
        float w = g_wsorted[i];
        float4 hv = *(const float4*)&g_h[c * HH + lane * 4];
        acc.x += w * hv.x; acc.y += w * hv.y;
        acc.z += w * hv.z; acc.w += w * hv.w;
    }
    const float s1 = 1.f - ALPHA;
    acc.x *= s1; acc.y *= s1; acc.z *= s1; acc.w *= s1;
    *(float4*)&g_p[row * HH + lane * 4] = acc;
}

// --------- layer GEMM: h = relu(h + (1-b)(p + a*x0) + b*(p@W1 + (a*x0)@W2)) ---------------
__global__ __launch_bounds__(256) void layer_gemm_kernel(const float* __restrict__ w1,
                                                         const float* __restrict__ w2,
                                                         float beta) {
    __shared__ float Ps[64][17];
    __shared__ float Xs[64][17];
    __shared__ float W1s[16][HH];
    __shared__ float W2s[16][HH];
    int tid = threadIdx.x;
    int tc = tid & 31;
    int tr = tid >> 5;
    int row0 = blockIdx.x * 64;

    float acc[8][4];
    #pragma unroll
    for (int i = 0; i < 8; i++)
        #pragma unroll
        for (int j = 0; j < 4; j++) acc[i][j] = 0.f;

    for (int k0 = 0; k0 < HH; k0 += 16) {
        {   // A tiles: 64x16 each -> 256 float4 each, 1 per thread
            int r = tid >> 2, kq = tid & 3;
            int gr = row0 + r;
            float4 pv = make_float4(0.f, 0.f, 0.f, 0.f), xv = pv;
            if (gr < NN) {
                pv = *(const float4*)&g_p[gr * HH + k0 + kq * 4];
                xv = *(const float4*)&g_x0[gr * HH + k0 + kq * 4];
            }
            Ps[r][kq * 4 + 0] = pv.x; Ps[r][kq * 4 + 1] = pv.y;
            Ps[r][kq * 4 + 2] = pv.z; Ps[r][kq * 4 + 3] = pv.w;
            Xs[r][kq * 4 + 0] = ALPHA * xv.x; Xs[r][kq * 4 + 1] = ALPHA * xv.y;
            Xs[r][kq * 4 + 2] = ALPHA * xv.z; Xs[r][kq * 4 + 3] = ALPHA * xv.w;
        }
        #pragma unroll
        for (int t = 0; t < 2; t++) {   // W tiles: 16x128 = 512 float4 each
            int f4 = tid + t * 256;
            int k = f4 >> 5, c4 = f4 & 31;
            *(float4*)&W1s[k][c4 * 4] = *(const float4*)&w1[(k0 + k) * HH + c4 * 4];
            *(float4*)&W2s[k][c4 * 4] = *(const float4*)&w2[(k0 + k) * HH + c4 * 4];
        }
        __syncthreads();
        #pragma unroll
        for (int k = 0; k < 16; k++) {
            float4 b1v = *(const float4*)&W1s[k][tc * 4];
            float4 b2v = *(const float4*)&W2s[k][tc * 4];
            #pragma unroll
            for (int i = 0; i < 8; i++) {
                float a1 = Ps[tr * 8 + i][k];
                float a2 = Xs[tr * 8 + i][k];
                acc[i][0] += a1 * b1v.x + a2 * b2v.x;
                acc[i][1] += a1 * b1v.y + a2 * b2v.y;
                acc[i][2] += a1 * b1v.z + a2 * b2v.z;
                acc[i][3] += a1 * b1v.w + a2 * b2v.w;
            }
        }
        __syncthreads();
    }
    float ob = 1.f - beta;
    #pragma unroll
    for (int i = 0; i < 8; i++) {
        int gr = row0 + tr * 8 + i;
        if (gr < NN) {
            int base = gr * HH + tc * 4;
            float4 hv = *(const float4*)&g_h[base];
            float4 pv = *(const float4*)&g_p[base];
            float4 xv = *(const float4*)&g_x0[base];
            float4 o;
            o.x = fmaxf(hv.x + ob * (pv.x + ALPHA * xv.x) + beta * acc[i][0], 0.f);
            o.y = fmaxf(hv.y + ob * (pv.y + ALPHA * xv.y) + beta * acc[i][1], 0.f);
            o.z = fmaxf(hv.z + ob * (pv.z + ALPHA * xv.z) + beta * acc[i][2], 0.f);
            o.w = fmaxf(hv.w + ob * (pv.w + ALPHA * xv.w) + beta * acc[i][3], 0.f);
            *(float4*)&g_h[base] = o;
        }
    }
}

// ------------------------- p_lc = log_softmax(h[:B] @ W2 + b2) -------------------------
__global__ __launch_bounds__(128) void plc_kernel(const float* __restrict__ W2,
                                                  const float* __restrict__ b2) {
    __shared__ float hrow[4][HH];
    int gw = (blockIdx.x * blockDim.x + threadIdx.x) >> 5;
    int lane = threadIdx.x & 31;
    int wl = threadIdx.x >> 5;
    if (gw >= BB) return;
    float4 hv = *(const float4*)&g_h[gw * HH + lane * 4];
    *(float4*)&hrow[wl][lane * 4] = hv;
    __syncwarp();
    float acc1 = 0.f, acc2 = 0.f;
    int c2 = lane + 32;
    for (int k = 0; k < HH; k++) {
        float h = hrow[wl][k];
        acc1 += h * W2[k * CC + lane];
        if (lane < 8) acc2 += h * W2[k * CC + c2];
    }
    acc1 += b2[lane];
    if (lane < 8) acc2 += b2[c2];
    float m = acc1;
    if (lane < 8) m = fmaxf(m, acc2);
    m = warp_max(m);
    float se = expf(acc1 - m) + ((lane < 8) ? expf(acc2 - m) : 0.f);
    se = warp_sum(se);
    float lse = m + logf(se);
    g_plc[gw * CC + lane] = acc1 - lse;
    if (lane < 8) g_plc[gw * CC + c2] = acc2 - lse;
}

// ------------------------- emb out + an = emb / max(||emb||, 1e-8) -------------------------
__global__ __launch_bounds__(128) void normalize_kernel(float* __restrict__ out_emb) {
    int gw = (blockIdx.x * blockDim.x + threadIdx.x) >> 5;
    int lane = threadIdx.x & 31;
    if (gw >= BB) return;
    float4 hv = *(const float4*)&g_h[gw * HH + lane * 4];
    *(float4*)&out_emb[gw * HH + lane * 4] = hv;
    float ss = hv.x * hv.x + hv.y * hv.y + hv.z * hv.z + hv.w * hv.w;
    ss = warp_sum(ss);
    float inv = 1.f / fmaxf(sqrtf(ss), 1e-8f);
    float4 a;
    a.x = hv.x * inv; a.y = hv.y * inv; a.z = hv.z * inv; a.w = hv.w * inv;
    *(float4*)&g_an[gw * HH + lane * 4] = a;
}

// ------------------------- sim = an @ an^T fused with row-wise top-5 -------------------------
// block: 256 threads = 16(tr) x 16(tc); tile 64 rows x 128 cols; per-thread 4x8 outputs.
#define ST_PAD_A 132
__global__ __launch_bounds__(256) void simtopk_kernel() {
    __shared__ float smem[64 * ST_PAD_A + HH * 17];   // 42.5 KB; reused for merge
    float* As = smem;                                  // [64][132]
    float* Bs = smem + 64 * ST_PAD_A;                  // [128][17]
    int tid = threadIdx.x;
    int tc = tid & 15;
    int tr = tid >> 4;
    int row0 = blockIdx.x * 64;

    #pragma unroll
    for (int t = 0; t < 8; t++) {    // A: 64x128 = 2048 float4
        int f4 = tid + t * 256;
        int r = f4 >> 5, c4 = f4 & 31;
        float4 v = make_float4(0.f, 0.f, 0.f, 0.f);
        if (row0 + r < BB) v = *(const float4*)&g_an[(row0 + r) * HH + c4 * 4];
        *(float4*)&As[r * ST_PAD_A + c4 * 4] = v;
    }
    __syncthreads();

    float topv[4][KK];
    int   topi[4][KK];
    #pragma unroll
    for (int i = 0; i < 4; i++)
        #pragma unroll
        for (int s = 0; s < KK; s++) { topv[i][s] = -1e30f; topi[i][s] = -1; }

    const int ntiles = (BB + 127) / 128;
    for (int tile = 0; tile < ntiles; tile++) {
        int col0 = tile * 128;
        float acc[4][8];
        #pragma unroll
        for (int i = 0; i < 4; i++)
            #pragma unroll
            for (int j = 0; j < 8; j++) acc[i][j] = 0.f;

        for (int k0 = 0; k0 < HH; k0 += 16) {
            #pragma unroll
            for (int t = 0; t < 2; t++) {   // B chunk: 128 cols x 16 k = 512 float4
                int f4 = tid + t * 256;
                int c = f4 >> 2, kq = f4 & 3;
                float4 v = make_float4(0.f, 0.f, 0.f, 0.f);
                if (col0 + c < BB) v = *(const float4*)&g_an[(col0 + c) * HH + k0 + kq * 4];
                Bs[c * 17 + kq * 4 + 0] = v.x;
                Bs[c * 17 + kq * 4 + 1] = v.y;
                Bs[c * 17 + kq * 4 + 2] = v.z;
                Bs[c * 17 + kq * 4 + 3] = v.w;
            }
            __syncthreads();
            #pragma unroll
            for (int k = 0; k < 16; k++) {
                float a[4], b[8];
                #pragma unroll
                for (int i = 0; i < 4; i++) a[i] = As[(tr * 4 + i) * ST_PAD_A + k0 + k];
                #pragma unroll
                for (int j = 0; j < 8; j++) b[j] = Bs[(j * 16 + tc) * 17 + k];
                #pragma unroll
                for (int i = 0; i < 4; i++)
                    #pragma unroll
                    for (int j = 0; j < 8; j++) acc[i][j] += a[i] * b[j];
            }
            __syncthreads();
        }
        #pragma unroll
        for (int j = 0; j < 8; j++) {
            int col = col0 + j * 16 + tc;
            if (col < BB) {
                #pragma unroll
                for (int i = 0; i < 4; i++) topk_insert(topv[i], topi[i], acc[i][j], col);
            }
        }
    }

    // merge: 16 partial top-5s per row -> final top-5
    __syncthreads();
    float* mv = smem;                 // [64][80]
    int*   mi = (int*)(smem + 64 * 80);
    #pragma unroll
    for (int i = 0; i < 4; i++) {
        int r = tr * 4 + i;
        #pragma unroll
        for (int s = 0; s < KK; s++) {
            mv[r * 80 + tc * KK + s] = topv[i][s];
            mi[r * 80 + tc * KK + s] = topi[i][s];
        }
    }
    __syncthreads();
    if (tid < 64) {
        int grow = row0 + tid;
        if (grow < BB) {
            float bv[KK]; int bi[KK];
            #pragma unroll
            for (int s = 0; s < KK; s++) { bv[s] = -1e30f; bi[s] = -1; }
            for (int s = 0; s < 80; s++)
                topk_insert(bv, bi, mv[tid * 80 + s], mi[tid * 80 + s]);
            #pragma unroll
            for (int s = 0; s < KK; s++) {
                g_topv[grow * KK + s] = bv[s];
                g_topi[grow * KK + s] = bi[s];
            }
        }
    }
}

// ------------------------- final = eta*p_lc + (1-eta)*log_softmax(fused) -------------------
__global__ __launch_bounds__(128) void final_kernel(const int* __restrict__ y,
                                                    float* __restrict__ out_final) {
    int gw = (blockIdx.x * blockDim.x + threadIdx.x) >> 5;
    int lane = threadIdx.x & 31;
    if (gw >= BB) return;
    float w[KK]; int yk[KK];
    #pragma unroll
    for (int s = 0; s < KK; s++) {
        float v = g_topv[gw * KK + s];
        int id = g_topi[gw * KK + s];
        w[s] = expf(v);
        yk[s] = y[id];
    }
    int c1 = lane, c2 = lane + 32;
    float f1 = 0.f, f2 = 0.f;
    #pragma unroll
    for (int s = 0; s < KK; s++) {
        if (yk[s] == c1) f1 += w[s];
        if (yk[s] == c2) f2 += w[s];
    }
    float m = f1;
    if (lane < 8) m = fmaxf(m, f2);
    m = warp_max(m);
    float se = expf(f1 - m) + ((lane < 8) ? expf(f2 - m) : 0.f);
    se = warp_sum(se);
    float lse = m + logf(se);
    float ps1 = f1 - lse;
    out_final[gw * CC + c1] = ETA * g_plc[gw * CC + c1] + (1.f - ETA) * ps1;
    if (lane < 8) {
        float ps2 = f2 - lse;
        out_final[gw * CC + c2] = ETA * g_plc[gw * CC + c2] + (1.f - ETA) * ps2;
    }
}

// ------------------------- launch -------------------------
extern "C" void kernel_launch(void* const* d_in, const int* in_sizes, int n_in,
                              void* d_out, int out_size) {
    const float* x  = (const float*)d_in[0];
    const int*   ei = (const int*)d_in[1];
    const float* ew = (const float*)d_in[2];
    const int*   y  = (const int*)d_in[3];
    int o = (n_in >= 11) ? 5 : 4;   // skip scalar batch_size if present
    const float* W1 = (const float*)d_in[o + 0];
    const float* b1 = (const float*)d_in[o + 1];
    const float* cw1 = (const float*)d_in[o + 2];
    const float* cw2 = (const float*)d_in[o + 3];
    const float* W2 = (const float*)d_in[o + 4];
    const float* b2 = (const float*)d_in[o + 5];
    float* out = (float*)d_out;
    float* out_final = out;
    float* out_emb = out + BB * CC;

    // CSR build
    zero_counts_kernel<<<(NN + 255) / 256, 256>>>();
    hist_kernel<<<(EE + 255) / 256, 256>>>(ei);
    scan_kernel<<<1, 1024>>>();
    csr_fill_kernel<<<(EE + 255) / 256, 256>>>(ei, ew);

    // input GEMM
    input_gemm_kernel<<<(NN + 63) / 64, 256>>>(x, W1, b1);

    // layers
    for (int l = 0; l < LL; l++) {
        float beta = (float)log(1.0 / (double)(l + 1) + 1.0);
        spmm_kernel<<<(NN * 32 + 255) / 256, 256>>>();
        layer_gemm_kernel<<<(NN + 63) / 64, 256>>>(cw1 + l * HH * HH, cw2 + l * HH * HH, beta);
    }

    // heads
    plc_kernel<<<(BB * 32 + 127) / 128, 128>>>(W2, b2);
    normalize_kernel<<<(BB * 32 + 127) / 128, 128>>>(out_emb);
    simtopk_kernel<<<(BB + 63) / 64, 256>>>();
    final_kernel<<<(BB * 32 + 127) / 128, 128>>>(y, out_final);
}

// round 4
// speedup vs baseline: 1.4095x; 1.4095x over previous
#include <cuda_runtime.h>
#include <cuda_bf16.h>
#include <math.h>

#define NN   50000
#define EE   800000
#define DIN_ 500
#define HH   128
#define CC   40
#define BB   10000
#define LL   9
#define KK   5
#define ALPHA 0.5f
#define ETA   0.5f
#define SW   12          // smem row width in 32-bit words (24 bf16, conflict-free pad)
#define NTL  79          // ceil(BB/128)
#define TPB_Y 20         // column tiles per y-split in simtopk

// ------------------------- scratch (device globals) -------------------------
__device__ float g_h[NN * HH];
__device__ __nv_bfloat16 g_p_hi[NN * HH], g_p_lo[NN * HH];
__device__ __nv_bfloat16 g_x0_hi[NN * HH], g_x0_lo[NN * HH];
__device__ __nv_bfloat16 g_an_hi[BB * HH], g_an_lo[BB * HH];
__device__ __nv_bfloat16 g_w1t_hi[HH * 512], g_w1t_lo[HH * 512];        // input W1^T padded K->512
__device__ __nv_bfloat16 g_wl1_hi[LL * HH * HH], g_wl1_lo[LL * HH * HH];
__device__ __nv_bfloat16 g_wl2_hi[LL * HH * HH], g_wl2_lo[LL * HH * HH];
__device__ int   g_cnt[NN];
__device__ int   g_fill[NN];
__device__ int   g_rowptr[NN + 1];
__device__ int   g_colidx[EE];
__device__ float g_wsorted[EE];
__device__ float g_plc[BB * CC];
__device__ float g_topvP[BB * 20];
__device__ int   g_topiP[BB * 20];

// ------------------------- helpers -------------------------
__device__ __forceinline__ float warp_max(float v) {
    #pragma unroll
    for (int o = 16; o > 0; o >>= 1) v = fmaxf(v, __shfl_xor_sync(0xffffffffu, v, o));
    return v;
}
__device__ __forceinline__ float warp_sum(float v) {
    #pragma unroll
    for (int o = 16; o > 0; o >>= 1) v += __shfl_xor_sync(0xffffffffu, v, o);
    return v;
}
__device__ __forceinline__ void split2(float a, float b, unsigned& hi, unsigned& lo) {
    __nv_bfloat16 ha = __float2bfloat16(a);
    __nv_bfloat16 hb = __float2bfloat16(b);
    float ra = a - __bfloat162float(ha);
    float rb = b - __bfloat162float(hb);
    __nv_bfloat16 la = __float2bfloat16(ra);
    __nv_bfloat16 lb = __float2bfloat16(rb);
    hi = (unsigned)(*(unsigned short*)&ha) | ((unsigned)(*(unsigned short*)&hb) << 16);
    lo = (unsigned)(*(unsigned short*)&la) | ((unsigned)(*(unsigned short*)&lb) << 16);
}

// top-5 insertion, sorted descending; ties -> lower index first
__device__ __forceinline__ void topk_insert(float (&tv)[KK], int (&ti)[KK], float v, int c) {
    if (v > tv[KK - 1] || (v == tv[KK - 1] && c < ti[KK - 1])) {
        tv[KK - 1] = v; ti[KK - 1] = c;
        #pragma unroll
        for (int p = KK - 1; p > 0; p--) {
            bool sw = (tv[p] > tv[p - 1]) || (tv[p] == tv[p - 1] && ti[p] < ti[p - 1]);
            if (sw) {
                float fv = tv[p]; tv[p] = tv[p - 1]; tv[p - 1] = fv;
                int fi = ti[p]; ti[p] = ti[p - 1]; ti[p - 1] = fi;
            }
        }
    }
}

__device__ __forceinline__ void mma_bf16(float d[4], const unsigned a[4], const unsigned b[2]) {
    asm volatile(
        "mma.sync.aligned.m16n8k16.row.col.f32.bf16.bf16.f32 "
        "{%0,%1,%2,%3}, {%4,%5,%6,%7}, {%8,%9}, {%0,%1,%2,%3};\n"
        : "+f"(d[0]), "+f"(d[1]), "+f"(d[2]), "+f"(d[3])
        : "r"(a[0]), "r"(a[1]), "r"(a[2]), "r"(a[3]), "r"(b[0]), "r"(b[1]));
}

// warp-level 32x64 tile compute from staged (hi,lo) bf16 tiles, one k16 step
__device__ __forceinline__ void mma_stage(const unsigned* Ah32, const unsigned* Al32,
                                          const unsigned* Bh32, const unsigned* Bl32,
                                          int wm, int wn, int g, int tg, float acc[2][8][4]) {
    unsigned ah[2][4], al[2][4];
    #pragma unroll
    for (int mf = 0; mf < 2; mf++) {
        int r = wm * 32 + mf * 16 + g;
        int b = r * SW + tg;
        ah[mf][0] = Ah32[b];          ah[mf][1] = Ah32[b + 8 * SW];
        ah[mf][2] = Ah32[b + 4];      ah[mf][3] = Ah32[b + 8 * SW + 4];
        al[mf][0] = Al32[b];          al[mf][1] = Al32[b + 8 * SW];
        al[mf][2] = Al32[b + 4];      al[mf][3] = Al32[b + 8 * SW + 4];
    }
    #pragma unroll
    for (int nf = 0; nf < 8; nf++) {
        int n = wn * 64 + nf * 8 + g;
        int bidx = n * SW + tg;
        unsigned bh[2] = {Bh32[bidx], Bh32[bidx + 4]};
        unsigned bl[2] = {Bl32[bidx], Bl32[bidx + 4]};
        #pragma unroll
        for (int mf = 0; mf < 2; mf++) {
            mma_bf16(acc[mf][nf], ah[mf], bh);
            mma_bf16(acc[mf][nf], ah[mf], bl);
            mma_bf16(acc[mf][nf], al[mf], bh);
        }
    }
}

// ------------------------- weight prep -------------------------
__global__ void prep_input_w_kernel(const float* __restrict__ W1) {
    int idx = blockIdx.x * blockDim.x + threadIdx.x;
    if (idx >= HH * 512) return;
    int n = idx >> 9, k = idx & 511;
    float v = (k < DIN_) ? W1[k * HH + n] : 0.f;
    __nv_bfloat16 hi = __float2bfloat16(v);
    __nv_bfloat16 lo = __float2bfloat16(v - __bfloat162float(hi));
    g_w1t_hi[idx] = hi; g_w1t_lo[idx] = lo;
}

// W1' = beta*W1 + (1-beta)*I  (applied to p, already scaled by (1-alpha))
// W2' = beta*W2 + (1-beta)*I  (applied to x0s which ALREADY carries alpha)
__global__ void prep_layer_w_kernel(const float* __restrict__ cw1, const float* __restrict__ cw2) {
    int idx = blockIdx.x * blockDim.x + threadIdx.x;
    if (idx >= LL * HH * HH) return;
    int l = idx / (HH * HH);
    int r = idx % (HH * HH);
    int n = r >> 7, k = r & 127;
    float beta = logf(1.f / (float)(l + 1) + 1.f);
    float diag = (n == k) ? (1.f - beta) : 0.f;
    float v1 = beta * cw1[l * HH * HH + k * HH + n] + diag;
    float v2 = beta * cw2[l * HH * HH + k * HH + n] + diag;
    __nv_bfloat16 h1 = __float2bfloat16(v1);
    g_wl1_hi[idx] = h1; g_wl1_lo[idx] = __float2bfloat16(v1 - __bfloat162float(h1));
    __nv_bfloat16 h2 = __float2bfloat16(v2);
    g_wl2_hi[idx] = h2; g_wl2_lo[idx] = __float2bfloat16(v2 - __bfloat162float(h2));
}

// ------------------------- CSR build -------------------------
__global__ void zero_counts_kernel() {
    int i = blockIdx.x * blockDim.x + threadIdx.x;
    if (i < NN) { g_cnt[i] = 0; g_fill[i] = 0; }
}
__global__ void hist_kernel(const int* __restrict__ ei) {
    int e = blockIdx.x * blockDim.x + threadIdx.x;
    if (e < EE) atomicAdd(&g_cnt[ei[e]], 1);
}
__global__ void scan_kernel() {
    __shared__ int sh[1024];
    int carry = 0;
    if (threadIdx.x == 0) g_rowptr[0] = 0;
    for (int base = 0; base < NN; base += 1024) {
        int i = base + threadIdx.x;
        int v = (i < NN) ? g_cnt[i] : 0;
        sh[threadIdx.x] = v;
        __syncthreads();
        #pragma unroll
        for (int off = 1; off < 1024; off <<= 1) {
            int t = 0;
            if (threadIdx.x >= off) t = sh[threadIdx.x - off];
            __syncthreads();
            sh[threadIdx.x] += t;
            __syncthreads();
        }
        if (i < NN) g_rowptr[i + 1] = carry + sh[threadIdx.x];
        carry += sh[1023];
        __syncthreads();
    }
}
__global__ void csr_fill_kernel(const int* __restrict__ ei, const float* __restrict__ ew) {
    int e = blockIdx.x * blockDim.x + threadIdx.x;
    if (e < EE) {
        int r = ei[e];
        int pos = g_rowptr[r] + atomicAdd(&g_fill[r], 1);
        g_colidx[pos] = ei[EE + e];
        g_wsorted[pos] = ew[e];
    }
}

// ------------------------- input GEMM (mma): h = relu(x@W1 + b1); x0s = alpha*h ----------
__global__ __launch_bounds__(256, 2) void input_mma_kernel(const float* __restrict__ x,
                                                           const float* __restrict__ b1) {
    __shared__ __align__(16) __nv_bfloat16 Ah[128 * 24], Al[128 * 24], Bh[128 * 24], Bl[128 * 24];
    const unsigned* Ah32 = (const unsigned*)Ah;
    const unsigned* Al32 = (const unsigned*)Al;
    const unsigned* Bh32 = (const unsigned*)Bh;
    const unsigned* Bl32 = (const unsigned*)Bl;
    int tid = threadIdx.x;
    int wid = tid >> 5, lane = tid & 31;
    int wm = wid & 3, wn = wid >> 2;
    int g = lane >> 2, tg = lane & 3;
    int row0 = blockIdx.x * 128;

    float acc[2][8][4];
    #pragma unroll
    for (int a = 0; a < 2; a++)
        #pragma unroll
        for (int b = 0; b < 8; b++)
            #pragma unroll
            for (int c = 0; c < 4; c++) acc[a][b][c] = 0.f;

    for (int k0 = 0; k0 < 512; k0 += 16) {
        if (tid < 128) {
            int grow = row0 + tid;
            float xv[16];
            #pragma unroll
            for (int c = 0; c < 4; c++) {
                if (grow < NN && (k0 + c * 4) < DIN_) {
                    float4 f = *(const float4*)&x[(size_t)grow * DIN_ + k0 + c * 4];
                    xv[c * 4 + 0] = f.x; xv[c * 4 + 1] = f.y; xv[c * 4 + 2] = f.z; xv[c * 4 + 3] = f.w;
                } else {
                    xv[c * 4 + 0] = 0.f; xv[c * 4 + 1] = 0.f; xv[c * 4 + 2] = 0.f; xv[c * 4 + 3] = 0.f;
                }
            }
            unsigned* ah = (unsigned*)Ah + tid * SW;
            unsigned* al = (unsigned*)Al + tid * SW;
            #pragma unroll
            for (int i = 0; i < 8; i++) {
                unsigned h, l;
                split2(xv[2 * i], xv[2 * i + 1], h, l);
                ah[i] = h; al[i] = l;
            }
        } else {
            int n = tid - 128;
            const uint4* sh = (const uint4*)&g_w1t_hi[n * 512 + k0];
            const uint4* sl = (const uint4*)&g_w1t_lo[n * 512 + k0];
            uint4* dh = (uint4*)&Bh[n * 24];
            uint4* dl = (uint4*)&Bl[n * 24];
            dh[0] = sh[0]; dh[1] = sh[1];
            dl[0] = sl[0]; dl[1] = sl[1];
        }
        __syncthreads();
        mma_stage(Ah32, Al32, Bh32, Bl32, wm, wn, g, tg, acc);
        __syncthreads();
    }

    #pragma unroll
    for (int mf = 0; mf < 2; mf++) {
        #pragma unroll
        for (int nf = 0; nf < 8; nf++) {
            int col = wn * 64 + nf * 8 + tg * 2;
            float2 bias = *(const float2*)&b1[col];
            #pragma unroll
            for (int h = 0; h < 2; h++) {
                int row = row0 + wm * 32 + mf * 16 + h * 8 + g;
                if (row < NN) {
                    float v0 = fmaxf(acc[mf][nf][h * 2 + 0] + bias.x, 0.f);
                    float v1 = fmaxf(acc[mf][nf][h * 2 + 1] + bias.y, 0.f);
                    *(float2*)&g_h[(size_t)row * HH + col] = make_float2(v0, v1);
                    unsigned hi, lo;
                    split2(ALPHA * v0, ALPHA * v1, hi, lo);
                    *(unsigned*)&g_x0_hi[(size_t)row * HH + col] = hi;
                    *(unsigned*)&g_x0_lo[(size_t)row * HH + col] = lo;
                }
            }
        }
    }
}

// ------------------------- SpMM: p = (1-alpha)*A@h -> bf16 hi/lo -------------------------
__global__ __launch_bounds__(256) void spmm_kernel() {
    int gt = blockIdx.x * blockDim.x + threadIdx.x;
    int row = gt >> 5;
    int lane = gt & 31;
    if (row >= NN) return;
    int s = g_rowptr[row], e = g_rowptr[row + 1];
    float4 acc = make_float4(0.f, 0.f, 0.f, 0.f);
    for (int i = s; i < e; i++) {
        int c = g_colidx[i];
        float w = g_wsorted[i];
        float4 hv = *(const float4*)&g_h[(size_t)c * HH + lane * 4];
        acc.x += w * hv.x; acc.y += w * hv.y;
        acc.z += w * hv.z; acc.w += w * hv.w;
    }
    const float s1 = 1.f - ALPHA;
    acc.x *= s1; acc.y *= s1; acc.z *= s1; acc.w *= s1;
    unsigned h0, l0, h1, l1;
    split2(acc.x, acc.y, h0, l0);
    split2(acc.z, acc.w, h1, l1);
    unsigned* ph = (unsigned*)&g_p_hi[(size_t)row * HH + lane * 4];
    unsigned* pl = (unsigned*)&g_p_lo[(size_t)row * HH + lane * 4];
    ph[0] = h0; ph[1] = h1;
    pl[0] = l0; pl[1] = l1;
}

// ------------------------- layer GEMM (mma): h = relu(h + p@W1' + x0s@W2') ---------------
__global__ __launch_bounds__(256, 2) void layer_mma_kernel(int l) {
    __shared__ __align__(16) __nv_bfloat16 Ah[128 * 24], Al[128 * 24], Bh[128 * 24], Bl[128 * 24];
    const unsigned* Ah32 = (const unsigned*)Ah;
    const unsigned* Al32 = (const unsigned*)Al;
    const unsigned* Bh32 = (const unsigned*)Bh;
    const unsigned* Bl32 = (const unsigned*)Bl;
    int tid = threadIdx.x;
    int wid = tid >> 5, lane = tid & 31;
    int wm = wid & 3, wn = wid >> 2;
    int g = lane >> 2, tg = lane & 3;
    int row0 = blockIdx.x * 128;
    const size_t wbase = (size_t)l * HH * HH;

    float acc[2][8][4];
    #pragma unroll
    for (int a = 0; a < 2; a++)
        #pragma unroll
        for (int b = 0; b < 8; b++)
            #pragma unroll
            for (int c = 0; c < 4; c++) acc[a][b][c] = 0.f;

    for (int k0 = 0; k0 < 256; k0 += 16) {
        if (tid < 128) {
            int grow = row0 + tid;
            uint4 v0 = make_uint4(0, 0, 0, 0), v1 = v0, u0 = v0, u1 = v0;
            if (grow < NN) {
                const __nv_bfloat16* sh;
                const __nv_bfloat16* sl;
                if (k0 < 128) { sh = g_p_hi + (size_t)grow * HH + k0;  sl = g_p_lo + (size_t)grow * HH + k0; }
                else          { sh = g_x0_hi + (size_t)grow * HH + (k0 - 128); sl = g_x0_lo + (size_t)grow * HH + (k0 - 128); }
                v0 = ((const uint4*)sh)[0]; v1 = ((const uint4*)sh)[1];
                u0 = ((const uint4*)sl)[0]; u1 = ((const uint4*)sl)[1];
            }
            uint4* dh = (uint4*)&Ah[tid * 24];
            uint4* dl = (uint4*)&Al[tid * 24];
            dh[0] = v0; dh[1] = v1;
            dl[0] = u0; dl[1] = u1;
        } else {
            int n = tid - 128;
            const __nv_bfloat16* sh;
            const __nv_bfloat16* sl;
            if (k0 < 128) { sh = g_wl1_hi + wbase + n * HH + k0;  sl = g_wl1_lo + wbase + n * HH + k0; }
            else          { sh = g_wl2_hi + wbase + n * HH + (k0 - 128); sl = g_wl2_lo + wbase + n * HH + (k0 - 128); }
            uint4* dh = (uint4*)&Bh[n * 24];
            uint4* dl = (uint4*)&Bl[n * 24];
            dh[0] = ((const uint4*)sh)[0]; dh[1] = ((const uint4*)sh)[1];
            dl[0] = ((const uint4*)sl)[0]; dl[1] = ((const uint4*)sl)[1];
        }
        __syncthreads();
        mma_stage(Ah32, Al32, Bh32, Bl32, wm, wn, g, tg, acc);
        __syncthreads();
    }

    #pragma unroll
    for (int mf = 0; mf < 2; mf++) {
        #pragma unroll
        for (int nf = 0; nf < 8; nf++) {
            int col = wn * 64 + nf * 8 + tg * 2;
            #pragma unroll
            for (int h = 0; h < 2; h++) {
                int row = row0 + wm * 32 + mf * 16 + h * 8 + g;
                if (row < NN) {
                    float2* hp = (float2*)&g_h[(size_t)row * HH + col];
                    float2 hv = *hp;
                    hv.x = fmaxf(hv.x + acc[mf][nf][h * 2 + 0], 0.f);
                    hv.y = fmaxf(hv.y + acc[mf][nf][h * 2 + 1], 0.f);
                    *hp = hv;
                }
            }
        }
    }
}

// ------------------------- p_lc = log_softmax(h[:B] @ W2 + b2) -------------------------
__global__ __launch_bounds__(128) void plc_kernel(const float* __restrict__ W2,
                                                  const float* __restrict__ b2) {
    __shared__ float hrow[4][HH];
    int gw = (blockIdx.x * blockDim.x + threadIdx.x) >> 5;
    int lane = threadIdx.x & 31;
    int wl = threadIdx.x >> 5;
    if (gw >= BB) return;
    float4 hv = *(const float4*)&g_h[(size_t)gw * HH + lane * 4];
    *(float4*)&hrow[wl][lane * 4] = hv;
    __syncwarp();
    float acc1 = 0.f, acc2 = 0.f;
    int c2 = lane + 32;
    for (int k = 0; k < HH; k++) {
        float h = hrow[wl][k];
        acc1 += h * W2[k * CC + lane];
        if (lane < 8) acc2 += h * W2[k * CC + c2];
    }
    acc1 += b2[lane];
    if (lane < 8) acc2 += b2[c2];
    float m = acc1;
    if (lane < 8) m = fmaxf(m, acc2);
    m = warp_max(m);
    float se = expf(acc1 - m) + ((lane < 8) ? expf(acc2 - m) : 0.f);
    se = warp_sum(se);
    float lse = m + logf(se);
    g_plc[gw * CC + lane] = acc1 - lse;
    if (lane < 8) g_plc[gw * CC + c2] = acc2 - lse;
}

// ------------------------- emb out + an split -------------------------
__global__ __launch_bounds__(128) void normalize_kernel(float* __restrict__ out_emb) {
    int gw = (blockIdx.x * blockDim.x + threadIdx.x) >> 5;
    int lane = threadIdx.x & 31;
    if (gw >= BB) return;
    float4 hv = *(const float4*)&g_h[(size_t)gw * HH + lane * 4];
    *(float4*)&out_emb[(size_t)gw * HH + lane * 4] = hv;
    float ss = hv.x * hv.x + hv.y * hv.y + hv.z * hv.z + hv.w * hv.w;
    ss = warp_sum(ss);
    float inv = 1.f / fmaxf(sqrtf(ss), 1e-8f);
    unsigned h0, l0, h1, l1;
    split2(hv.x * inv, hv.y * inv, h0, l0);
    split2(hv.z * inv, hv.w * inv, h1, l1);
    unsigned* ph = (unsigned*)&g_an_hi[(size_t)gw * HH + lane * 4];
    unsigned* pl = (unsigned*)&g_an_lo[(size_t)gw * HH + lane * 4];
    ph[0] = h0; ph[1] = h1;
    pl[0] = l0; pl[1] = l1;
}

// ------------------------- sim + top-5 (mma, 4-way column split) -------------------------
__global__ __launch_bounds__(256, 1) void simtopk_mma_kernel() {
    __shared__ __align__(16) unsigned char S[40960];
    __nv_bfloat16* Ah = (__nv_bfloat16*)(S);
    __nv_bfloat16* Al = (__nv_bfloat16*)(S + 6144);
    __nv_bfloat16* Bh = (__nv_bfloat16*)(S + 12288);
    __nv_bfloat16* Bl = (__nv_bfloat16*)(S + 18432);
    const unsigned* Ah32 = (const unsigned*)Ah;
    const unsigned* Al32 = (const unsigned*)Al;
    const unsigned* Bh32 = (const unsigned*)Bh;
    const unsigned* Bl32 = (const unsigned*)Bl;
    int tid = threadIdx.x;
    int wid = tid >> 5, lane = tid & 31;
    int wm = wid & 3, wn = wid >> 2;
    int g = lane >> 2, tg = lane & 3;
    int row0 = blockIdx.x * 128;
    int tstart = blockIdx.y * TPB_Y;
    int tend = min(NTL, tstart + TPB_Y);

    float tv[2][2][KK];
    int   ti[2][2][KK];
    #pragma unroll
    for (int a = 0; a < 2; a++)
        #pragma unroll
        for (int b = 0; b < 2; b++)
            #pragma unroll
            for (int s = 0; s < KK; s++) { tv[a][b][s] = -1e30f; ti[a][b][s] = -1; }

    for (int ct = tstart; ct < tend; ct++) {
        int col0 = ct * 128;
        float acc[2][8][4];
        #pragma unroll
        for (int a = 0; a < 2; a++)
            #pragma unroll
            for (int b = 0; b < 8; b++)
                #pragma unroll
                for (int c = 0; c < 4; c++) acc[a][b][c] = 0.f;

        for (int k0 = 0; k0 < HH; k0 += 16) {
            if (tid < 128) {
                int row = row0 + tid;
                uint4 v0 = make_uint4(0, 0, 0, 0), v1 = v0, u0 = v0, u1 = v0;
                if (row < BB) {
                    v0 = ((const uint4*)&g_an_hi[(size_t)row * HH + k0])[0];
                    v1 = ((const uint4*)&g_an_hi[(size_t)row * HH + k0])[1];
                    u0 = ((const uint4*)&g_an_lo[(size_t)row * HH + k0])[0];
                    u1 = ((const uint4*)&g_an_lo[(size_t)row * HH + k0])[1];
                }
                uint4* dh = (uint4*)&Ah[tid * 24];
                uint4* dl = (uint4*)&Al[tid * 24];
                dh[0] = v0; dh[1] = v1;
                dl[0] = u0; dl[1] = u1;
            } else {
                int n = col0 + (tid - 128);
                uint4 v0 = make_uint4(0, 0, 0, 0), v1 = v0, u0 = v0, u1 = v0;
                if (n < BB) {
                    v0 = ((const uint4*)&g_an_hi[(size_t)n * HH + k0])[0];
                    v1 = ((const uint4*)&g_an_hi[(size_t)n * HH + k0])[1];
                    u0 = ((const uint4*)&g_an_lo[(size_t)n * HH + k0])[0];
                    u1 = ((const uint4*)&g_an_lo[(size_t)n * HH + k0])[1];
                }
                uint4* dh = (uint4*)&Bh[(tid - 128) * 24];
                uint4* dl = (uint4*)&Bl[(tid - 128) * 24];
                dh[0] = v0; dh[1] = v1;
                dl[0] = u0; dl[1] = u1;
            }
            __syncthreads();
            mma_stage(Ah32, Al32, Bh32, Bl32, wm, wn, g, tg, acc);
            __syncthreads();
        }

        #pragma unroll
        for (int mf = 0; mf < 2; mf++) {
            #pragma unroll
            for (int nf = 0; nf < 8; nf++) {
                int c0 = col0 + wn * 64 + nf * 8 + tg * 2;
                if (c0 < BB)     { topk_insert(tv[mf][0], ti[mf][0], acc[mf][nf][0], c0);
                                   topk_insert(tv[mf][1], ti[mf][1], acc[mf][nf][2], c0); }
                if (c0 + 1 < BB) { topk_insert(tv[mf][0], ti[mf][0], acc[mf][nf][1], c0 + 1);
                                   topk_insert(tv[mf][1], ti[mf][1], acc[mf][nf][3], c0 + 1); }
            }
        }
    }

    // Stage 1: shuffle-merge across the 4 tg lanes (same rows, different col subsets).
    #pragma unroll
    for (int off = 2; off >= 1; off >>= 1) {
        #pragma unroll
        for (int mf = 0; mf < 2; mf++)
            #pragma unroll
            for (int h = 0; h < 2; h++) {
                float ov[KK]; int oi[KK];
                #pragma unroll
                for (int s = 0; s < KK; s++) {
                    ov[s] = __shfl_down_sync(0xffffffffu, tv[mf][h][s], off);
                    oi[s] = __shfl_down_sync(0xffffffffu, ti[mf][h][s], off);
                }
                if (tg < off) {
                    #pragma unroll
                    for (int s = 0; s < KK; s++) topk_insert(tv[mf][h], ti[mf][h], ov[s], oi[s]);
                }
            }
    }

    // Stage 2: 2 partials per row (one per wn in [0,2)) via smem [128][10]
    __syncthreads();
    float* mv = (float*)S;                  // 128*10*4 = 5120 B
    int*   mi = (int*)(S + 5120);           // 5120 B
    if (tg == 0) {
        #pragma unroll
        for (int mf = 0; mf < 2; mf++)
            #pragma unroll
            for (int h = 0; h < 2; h++) {
                int rb = wm * 32 + mf * 16 + h * 8 + g;
                #pragma unroll
                for (int s = 0; s < KK; s++) {
                    mv[rb * 10 + wn * KK + s] = tv[mf][h][s];
                    mi[rb * 10 + wn * KK + s] = ti[mf][h][s];
                }
            }
    }
    __syncthreads();
    if (tid < 128) {
        int grow = row0 + tid;
        if (grow < BB) {
            float bv[KK]; int bi[KK];
            #pragma unroll
            for (int s = 0; s < KK; s++) { bv[s] = -1e30f; bi[s] = -1; }
            #pragma unroll
            for (int s = 0; s < 10; s++)
                topk_insert(bv, bi, mv[tid * 10 + s], mi[tid * 10 + s]);
            #pragma unroll
            for (int s = 0; s < KK; s++) {
                g_topvP[grow * 20 + blockIdx.y * KK + s] = bv[s];
                g_topiP[grow * 20 + blockIdx.y * KK + s] = bi[s];
            }
        }
    }
}

// ------------------------- final = eta*p_lc + (1-eta)*log_softmax(fused) -------------------
__global__ __launch_bounds__(128) void final_kernel(const int* __restrict__ y,
                                                    float* __restrict__ out_final) {
    int gw = (blockIdx.x * blockDim.x + threadIdx.x) >> 5;
    int lane = threadIdx.x & 31;
    if (gw >= BB) return;
    float bv[KK]; int bi[KK];
    #pragma unroll
    for (int s = 0; s < KK; s++) { bv[s] = -1e30f; bi[s] = -1; }
    #pragma unroll
    for (int s = 0; s < 20; s++)
        topk_insert(bv, bi, g_topvP[gw * 20 + s], g_topiP[gw * 20 + s]);
    float w[KK]; int yk[KK];
    #pragma unroll
    for (int s = 0; s < KK; s++) {
        w[s] = expf(bv[s]);
        int id = bi[s];
        if (id < 0) id = 0;          // defensive: never true on correct runs
        if (id >= BB) id = BB - 1;
        yk[s] = y[id];
    }
    int c1 = lane, c2 = lane + 32;
    float f1 = 0.f, f2 = 0.f;
    #pragma unroll
    for (int s = 0; s < KK; s++) {
        if (yk[s] == c1) f1 += w[s];
        if (yk[s] == c2) f2 += w[s];
    }
    float m = f1;
    if (lane < 8) m = fmaxf(m, f2);
    m = warp_max(m);
    float se = expf(f1 - m) + ((lane < 8) ? expf(f2 - m) : 0.f);
    se = warp_sum(se);
    float lse = m + logf(se);
    float ps1 = f1 - lse;
    out_final[gw * CC + c1] = ETA * g_plc[gw * CC + c1] + (1.f - ETA) * ps1;
    if (lane < 8) {
        float ps2 = f2 - lse;
        out_final[gw * CC + c2] = ETA * g_plc[gw * CC + c2] + (1.f - ETA) * ps2;
    }
}

// ------------------------- launch -------------------------
extern "C" void kernel_launch(void* const* d_in, const int* in_sizes, int n_in,
                              void* d_out, int out_size) {
    const float* x  = (const float*)d_in[0];
    const int*   ei = (const int*)d_in[1];
    const float* ew = (const float*)d_in[2];
    const int*   y  = (const int*)d_in[3];
    int o = (n_in >= 11) ? 5 : 4;
    const float* W1 = (const float*)d_in[o + 0];
    const float* b1 = (const float*)d_in[o + 1];
    const float* cw1 = (const float*)d_in[o + 2];
    const float* cw2 = (const float*)d_in[o + 3];
    const float* W2 = (const float*)d_in[o + 4];
    const float* b2 = (const float*)d_in[o + 5];
    float* out = (float*)d_out;
    float* out_final = out;
    float* out_emb = out + BB * CC;

    // weight prep
    prep_input_w_kernel<<<(HH * 512 + 255) / 256, 256>>>(W1);
    prep_layer_w_kernel<<<(LL * HH * HH + 255) / 256, 256>>>(cw1, cw2);

    // CSR build
    zero_counts_kernel<<<(NN + 255) / 256, 256>>>();
    hist_kernel<<<(EE + 255) / 256, 256>>>(ei);
    scan_kernel<<<1, 1024>>>();
    csr_fill_kernel<<<(EE + 255) / 256, 256>>>(ei, ew);

    // input GEMM
    input_mma_kernel<<<(NN + 127) / 128, 256>>>(x, b1);

    // layers
    for (int l = 0; l < LL; l++) {
        spmm_kernel<<<(NN * 32 + 255) / 256, 256>>>();
        layer_mma_kernel<<<(NN + 127) / 128, 256>>>(l);
    }

    // heads
    plc_kernel<<<(BB * 32 + 127) / 128, 128>>>(W2, b2);
    normalize_kernel<<<(BB * 32 + 127) / 128, 128>>>(out_emb);
    simtopk_mma_kernel<<<dim3(NTL, 4), 256>>>();
    final_kernel<<<(BB * 32 + 127) / 128, 128>>>(y, out_final);
}

// round 5
// speedup vs baseline: 1.8565x; 1.3171x over previous
#include <cuda_runtime.h>
#include <cuda_bf16.h>
#include <math.h>

#define NN   50000
#define EE   800000
#define DIN_ 500
#define HH   128
#define CC   40
#define BB   10000
#define LL   9
#define KK   5
#define ALPHA 0.5f
#define ETA   0.5f

#define RS_L 36          // smem row stride in words for 64-k chunks (32 words + 4 pad)
#define RS_S 68          // smem row stride in words for 128-k tiles (64 words + 4 pad)
#define NTL  79          // ceil(BB/128)
#define YS   7           // y-splits in simtopk
#define TPB_Y 12         // column tiles per y-split (7*12 >= 79)
#define NPART (YS * KK)  // 35 partial slots per row

// ------------------------- scratch (device globals) -------------------------
__device__ float g_h[NN * HH];
__device__ __nv_bfloat16 g_p_hi[NN * HH], g_p_lo[NN * HH];
__device__ __nv_bfloat16 g_x0_hi[NN * HH], g_x0_lo[NN * HH];
__device__ __nv_bfloat16 g_an_hi[BB * HH], g_an_lo[BB * HH];
__device__ __nv_bfloat16 g_w1t_hi[HH * 512], g_w1t_lo[HH * 512];
__device__ __nv_bfloat16 g_wl1_hi[LL * HH * HH], g_wl1_lo[LL * HH * HH];
__device__ __nv_bfloat16 g_wl2_hi[LL * HH * HH], g_wl2_lo[LL * HH * HH];
__device__ int   g_cnt[NN];
__device__ int   g_fill[NN];
__device__ int   g_rowptr[NN + 1];
__device__ int   g_colidx[EE];
__device__ float g_wsorted[EE];
__device__ float g_plc[BB * CC];
__device__ float g_topvP[BB * NPART];
__device__ int   g_topiP[BB * NPART];

// ------------------------- helpers -------------------------
__device__ __forceinline__ float warp_max(float v) {
    #pragma unroll
    for (int o = 16; o > 0; o >>= 1) v = fmaxf(v, __shfl_xor_sync(0xffffffffu, v, o));
    return v;
}
__device__ __forceinline__ float warp_sum(float v) {
    #pragma unroll
    for (int o = 16; o > 0; o >>= 1) v += __shfl_xor_sync(0xffffffffu, v, o);
    return v;
}
__device__ __forceinline__ void split2(float a, float b, unsigned& hi, unsigned& lo) {
    __nv_bfloat16 ha = __float2bfloat16(a);
    __nv_bfloat16 hb = __float2bfloat16(b);
    float ra = a - __bfloat162float(ha);
    float rb = b - __bfloat162float(hb);
    __nv_bfloat16 la = __float2bfloat16(ra);
    __nv_bfloat16 lb = __float2bfloat16(rb);
    hi = (unsigned)(*(unsigned short*)&ha) | ((unsigned)(*(unsigned short*)&hb) << 16);
    lo = (unsigned)(*(unsigned short*)&la) | ((unsigned)(*(unsigned short*)&lb) << 16);
}

// top-5 insertion, sorted descending; ties -> lower index first
__device__ __forceinline__ void topk_insert(float (&tv)[KK], int (&ti)[KK], float v, int c) {
    if (v > tv[KK - 1] || (v == tv[KK - 1] && c < ti[KK - 1])) {
        tv[KK - 1] = v; ti[KK - 1] = c;
        #pragma unroll
        for (int p = KK - 1; p > 0; p--) {
            bool sw = (tv[p] > tv[p - 1]) || (tv[p] == tv[p - 1] && ti[p] < ti[p - 1]);
            if (sw) {
                float fv = tv[p]; tv[p] = tv[p - 1]; tv[p - 1] = fv;
                int fi = ti[p]; ti[p] = ti[p - 1]; ti[p - 1] = fi;
            }
        }
    }
}

__device__ __forceinline__ void mma_bf16(float d[4], const unsigned a[4], const unsigned b[2]) {
    asm volatile(
        "mma.sync.aligned.m16n8k16.row.col.f32.bf16.bf16.f32 "
        "{%0,%1,%2,%3}, {%4,%5,%6,%7}, {%8,%9}, {%0,%1,%2,%3};\n"
        : "+f"(d[0]), "+f"(d[1]), "+f"(d[2]), "+f"(d[3])
        : "r"(a[0]), "r"(a[1]), "r"(a[2]), "r"(a[3]), "r"(b[0]), "r"(b[1]));
}

// warp 32x64 tile; NK k16-steps from staged (hi,lo) tiles with row stride RS words
template<int RS, int NK>
__device__ __forceinline__ void mma_chunk(const unsigned* Ah32, const unsigned* Al32,
                                          const unsigned* Bh32, const unsigned* Bl32,
                                          int wm, int wn, int g, int tg, float acc[2][8][4]) {
    #pragma unroll
    for (int ks = 0; ks < NK; ks++) {
        int ko = ks * 8;
        unsigned ah[2][4], al[2][4];
        #pragma unroll
        for (int mf = 0; mf < 2; mf++) {
            int r = wm * 32 + mf * 16 + g;
            int b = r * RS + ko + tg;
            ah[mf][0] = Ah32[b];          ah[mf][1] = Ah32[b + 8 * RS];
            ah[mf][2] = Ah32[b + 4];      ah[mf][3] = Ah32[b + 8 * RS + 4];
            al[mf][0] = Al32[b];          al[mf][1] = Al32[b + 8 * RS];
            al[mf][2] = Al32[b + 4];      al[mf][3] = Al32[b + 8 * RS + 4];
        }
        #pragma unroll
        for (int nf = 0; nf < 8; nf++) {
            int n = wn * 64 + nf * 8 + g;
            int bidx = n * RS + ko + tg;
            unsigned bh[2] = {Bh32[bidx], Bh32[bidx + 4]};
            unsigned bl[2] = {Bl32[bidx], Bl32[bidx + 4]};
            #pragma unroll
            for (int mf = 0; mf < 2; mf++) {
                mma_bf16(acc[mf][nf], ah[mf], bh);
                mma_bf16(acc[mf][nf], ah[mf], bl);
                mma_bf16(acc[mf][nf], al[mf], bh);
            }
        }
    }
}

// ------------------------- weight prep -------------------------
__global__ void prep_input_w_kernel(const float* __restrict__ W1) {
    int idx = blockIdx.x * blockDim.x + threadIdx.x;
    if (idx >= HH * 512) return;
    int n = idx >> 9, k = idx & 511;
    float v = (k < DIN_) ? W1[k * HH + n] : 0.f;
    __nv_bfloat16 hi = __float2bfloat16(v);
    __nv_bfloat16 lo = __float2bfloat16(v - __bfloat162float(hi));
    g_w1t_hi[idx] = hi; g_w1t_lo[idx] = lo;
}

__global__ void prep_layer_w_kernel(const float* __restrict__ cw1, const float* __restrict__ cw2) {
    int idx = blockIdx.x * blockDim.x + threadIdx.x;
    if (idx >= LL * HH * HH) return;
    int l = idx / (HH * HH);
    int r = idx % (HH * HH);
    int n = r >> 7, k = r & 127;
    float beta = logf(1.f / (float)(l + 1) + 1.f);
    float diag = (n == k) ? (1.f - beta) : 0.f;
    float v1 = beta * cw1[l * HH * HH + k * HH + n] + diag;
    float v2 = beta * cw2[l * HH * HH + k * HH + n] + diag;
    __nv_bfloat16 h1 = __float2bfloat16(v1);
    g_wl1_hi[idx] = h1; g_wl1_lo[idx] = __float2bfloat16(v1 - __bfloat162float(h1));
    __nv_bfloat16 h2 = __float2bfloat16(v2);
    g_wl2_hi[idx] = h2; g_wl2_lo[idx] = __float2bfloat16(v2 - __bfloat162float(h2));
}

// ------------------------- CSR build -------------------------
__global__ void zero_counts_kernel() {
    int i = blockIdx.x * blockDim.x + threadIdx.x;
    if (i < NN) { g_cnt[i] = 0; g_fill[i] = 0; }
}
__global__ void hist_kernel(const int* __restrict__ ei) {
    int e = blockIdx.x * blockDim.x + threadIdx.x;
    if (e < EE) atomicAdd(&g_cnt[ei[e]], 1);
}
__global__ void scan_kernel() {
    __shared__ int sh[1024];
    int carry = 0;
    if (threadIdx.x == 0) g_rowptr[0] = 0;
    for (int base = 0; base < NN; base += 1024) {
        int i = base + threadIdx.x;
        int v = (i < NN) ? g_cnt[i] : 0;
        sh[threadIdx.x] = v;
        __syncthreads();
        #pragma unroll
        for (int off = 1; off < 1024; off <<= 1) {
            int t = 0;
            if (threadIdx.x >= off) t = sh[threadIdx.x - off];
            __syncthreads();
            sh[threadIdx.x] += t;
            __syncthreads();
        }
        if (i < NN) g_rowptr[i + 1] = carry + sh[threadIdx.x];
        carry += sh[1023];
        __syncthreads();
    }
}
__global__ void csr_fill_kernel(const int* __restrict__ ei, const float* __restrict__ ew) {
    int e = blockIdx.x * blockDim.x + threadIdx.x;
    if (e < EE) {
        int r = ei[e];
        int pos = g_rowptr[r] + atomicAdd(&g_fill[r], 1);
        g_colidx[pos] = ei[EE + e];
        g_wsorted[pos] = ew[e];
    }
}

// ------------------------- input GEMM (mma): h = relu(x@W1 + b1); x0s = alpha*h ----------
__global__ __launch_bounds__(256) void input_mma_kernel(const float* __restrict__ x,
                                                        const float* __restrict__ b1) {
    extern __shared__ __align__(16) unsigned char S[];
    const int SZ = 128 * RS_L * 4;    // 18432 B per array
    unsigned* Ah32 = (unsigned*)S;
    unsigned* Al32 = (unsigned*)(S + SZ);
    unsigned* Bh32 = (unsigned*)(S + 2 * SZ);
    unsigned* Bl32 = (unsigned*)(S + 3 * SZ);
    uint4* Bh4 = (uint4*)Bh32;
    uint4* Bl4 = (uint4*)Bl32;
    int tid = threadIdx.x;
    int wid = tid >> 5, lane = tid & 31;
    int wm = wid & 3, wn = wid >> 2;
    int g = lane >> 2, tg = lane & 3;
    int row0 = blockIdx.x * 128;

    float acc[2][8][4];
    #pragma unroll
    for (int a = 0; a < 2; a++)
        #pragma unroll
        for (int b = 0; b < 8; b++)
            #pragma unroll
            for (int c = 0; c < 4; c++) acc[a][b][c] = 0.f;

    for (int c = 0; c < 8; c++) {
        int k0 = c * 64;
        // A: x fp32 -> split to bf16 hi/lo (DIN_=500 = 125 float4s; pad beyond with 0)
        #pragma unroll
        for (int t = 0; t < 8; t++) {
            int idx = tid + t * 256;     // 0..2047
            int r = idx >> 4, q = idx & 15;
            int grow = row0 + r;
            int kk = k0 + q * 4;
            float4 f = make_float4(0.f, 0.f, 0.f, 0.f);
            if (grow < NN && kk < DIN_)
                f = *(const float4*)&x[(size_t)grow * DIN_ + kk];
            unsigned h0, l0, h1, l1;
            split2(f.x, f.y, h0, l0);
            split2(f.z, f.w, h1, l1);
            int w = r * RS_L + q * 2;
            Ah32[w] = h0; Ah32[w + 1] = h1;
            Al32[w] = l0; Al32[w + 1] = l1;
        }
        // B: prepped transposed weights (contiguous 512-k rows)
        #pragma unroll
        for (int t = 0; t < 4; t++) {
            int idx = tid + t * 256;     // 0..1023
            int n = idx >> 3, j = idx & 7;
            Bh4[n * 9 + j] = ((const uint4*)(g_w1t_hi + n * 512 + k0))[j];
            Bl4[n * 9 + j] = ((const uint4*)(g_w1t_lo + n * 512 + k0))[j];
        }
        __syncthreads();
        mma_chunk<RS_L, 4>(Ah32, Al32, Bh32, Bl32, wm, wn, g, tg, acc);
        __syncthreads();
    }

    #pragma unroll
    for (int mf = 0; mf < 2; mf++) {
        #pragma unroll
        for (int nf = 0; nf < 8; nf++) {
            int col = wn * 64 + nf * 8 + tg * 2;
            float2 bias = *(const float2*)&b1[col];
            #pragma unroll
            for (int h = 0; h < 2; h++) {
                int row = row0 + wm * 32 + mf * 16 + h * 8 + g;
                if (row < NN) {
                    float v0 = fmaxf(acc[mf][nf][h * 2 + 0] + bias.x, 0.f);
                    float v1 = fmaxf(acc[mf][nf][h * 2 + 1] + bias.y, 0.f);
                    *(float2*)&g_h[(size_t)row * HH + col] = make_float2(v0, v1);
                    unsigned hi, lo;
                    split2(ALPHA * v0, ALPHA * v1, hi, lo);
                    *(unsigned*)&g_x0_hi[(size_t)row * HH + col] = hi;
                    *(unsigned*)&g_x0_lo[(size_t)row * HH + col] = lo;
                }
            }
        }
    }
}

// ------------------------- SpMM: p = (1-alpha)*A@h -> bf16 hi/lo -------------------------
__global__ __launch_bounds__(256) void spmm_kernel() {
    int gt = blockIdx.x * blockDim.x + threadIdx.x;
    int row = gt >> 5;
    int lane = gt & 31;
    if (row >= NN) return;
    int s = g_rowptr[row], e = g_rowptr[row + 1];
    float4 acc = make_float4(0.f, 0.f, 0.f, 0.f);
    for (int i = s; i < e; i++) {
        int c = g_colidx[i];
        float w = g_wsorted[i];
        float4 hv = *(const float4*)&g_h[(size_t)c * HH + lane * 4];
        acc.x += w * hv.x; acc.y += w * hv.y;
        acc.z += w * hv.z; acc.w += w * hv.w;
    }
    const float s1 = 1.f - ALPHA;
    acc.x *= s1; acc.y *= s1; acc.z *= s1; acc.w *= s1;
    unsigned h0, l0, h1, l1;
    split2(acc.x, acc.y, h0, l0);
    split2(acc.z, acc.w, h1, l1);
    unsigned* ph = (unsigned*)&g_p_hi[(size_t)row * HH + lane * 4];
    unsigned* pl = (unsigned*)&g_p_lo[(size_t)row * HH + lane * 4];
    ph[0] = h0; ph[1] = h1;
    pl[0] = l0; pl[1] = l1;
}

// ------------------------- layer GEMM (mma): h = relu(h + p@W1' + x0s@W2') ---------------
__global__ __launch_bounds__(256) void layer_mma_kernel(int l) {
    extern __shared__ __align__(16) unsigned char S[];
    const int SZ = 128 * RS_L * 4;
    unsigned* Ah32 = (unsigned*)S;
    unsigned* Al32 = (unsigned*)(S + SZ);
    unsigned* Bh32 = (unsigned*)(S + 2 * SZ);
    unsigned* Bl32 = (unsigned*)(S + 3 * SZ);
    uint4* Ah4 = (uint4*)Ah32;
    uint4* Al4 = (uint4*)Al32;
    uint4* Bh4 = (uint4*)Bh32;
    uint4* Bl4 = (uint4*)Bl32;
    int tid = threadIdx.x;
    int wid = tid >> 5, lane = tid & 31;
    int wm = wid & 3, wn = wid >> 2;
    int g = lane >> 2, tg = lane & 3;
    int row0 = blockIdx.x * 128;
    const size_t wbase = (size_t)l * HH * HH;

    float acc[2][8][4];
    #pragma unroll
    for (int a = 0; a < 2; a++)
        #pragma unroll
        for (int b = 0; b < 8; b++)
            #pragma unroll
            for (int c = 0; c < 4; c++) acc[a][b][c] = 0.f;

    #pragma unroll
    for (int c = 0; c < 4; c++) {
        int koff = (c & 1) * 64;
        const __nv_bfloat16 *ah_src, *al_src, *bh_src, *bl_src;
        if (c < 2) { ah_src = g_p_hi;  al_src = g_p_lo;
                     bh_src = g_wl1_hi + wbase; bl_src = g_wl1_lo + wbase; }
        else       { ah_src = g_x0_hi; al_src = g_x0_lo;
                     bh_src = g_wl2_hi + wbase; bl_src = g_wl2_lo + wbase; }
        #pragma unroll
        for (int t = 0; t < 4; t++) {
            int idx = tid + t * 256;     // 0..1023
            int r = idx >> 3, j = idx & 7;
            int grow = row0 + r;
            uint4 vh = make_uint4(0, 0, 0, 0), vl = vh;
            if (grow < NN) {
                vh = ((const uint4*)(ah_src + (size_t)grow * HH + koff))[j];
                vl = ((const uint4*)(al_src + (size_t)grow * HH + koff))[j];
            }
            Ah4[r * 9 + j] = vh; Al4[r * 9 + j] = vl;
            Bh4[r * 9 + j] = ((const uint4*)(bh_src + r * HH + koff))[j];
            Bl4[r * 9 + j] = ((const uint4*)(bl_src + r * HH + koff))[j];
        }
        __syncthreads();
        mma_chunk<RS_L, 4>(Ah32, Al32, Bh32, Bl32, wm, wn, g, tg, acc);
        __syncthreads();
    }

    #pragma unroll
    for (int mf = 0; mf < 2; mf++) {
        #pragma unroll
        for (int nf = 0; nf < 8; nf++) {
            int col = wn * 64 + nf * 8 + tg * 2;
            #pragma unroll
            for (int h = 0; h < 2; h++) {
                int row = row0 + wm * 32 + mf * 16 + h * 8 + g;
                if (row < NN) {
                    float2* hp = (float2*)&g_h[(size_t)row * HH + col];
                    float2 hv = *hp;
                    hv.x = fmaxf(hv.x + acc[mf][nf][h * 2 + 0], 0.f);
                    hv.y = fmaxf(hv.y + acc[mf][nf][h * 2 + 1], 0.f);
                    *hp = hv;
                }
            }
        }
    }
}

// ------------------------- p_lc = log_softmax(h[:B] @ W2 + b2) -------------------------
__global__ __launch_bounds__(128) void plc_kernel(const float* __restrict__ W2,
                                                  const float* __restrict__ b2) {
    __shared__ float hrow[4][HH];
    int gw = (blockIdx.x * blockDim.x + threadIdx.x) >> 5;
    int lane = threadIdx.x & 31;
    int wl = threadIdx.x >> 5;
    if (gw >= BB) return;
    float4 hv = *(const float4*)&g_h[(size_t)gw * HH + lane * 4];
    *(float4*)&hrow[wl][lane * 4] = hv;
    __syncwarp();
    float acc1 = 0.f, acc2 = 0.f;
    int c2 = lane + 32;
    for (int k = 0; k < HH; k++) {
        float h = hrow[wl][k];
        acc1 += h * W2[k * CC + lane];
        if (lane < 8) acc2 += h * W2[k * CC + c2];
    }
    acc1 += b2[lane];
    if (lane < 8) acc2 += b2[c2];
    float m = acc1;
    if (lane < 8) m = fmaxf(m, acc2);
    m = warp_max(m);
    float se = expf(acc1 - m) + ((lane < 8) ? expf(acc2 - m) : 0.f);
    se = warp_sum(se);
    float lse = m + logf(se);
    g_plc[gw * CC + lane] = acc1 - lse;
    if (lane < 8) g_plc[gw * CC + c2] = acc2 - lse;
}

// ------------------------- emb out + an split -------------------------
__global__ __launch_bounds__(128) void normalize_kernel(float* __restrict__ out_emb) {
    int gw = (blockIdx.x * blockDim.x + threadIdx.x) >> 5;
    int lane = threadIdx.x & 31;
    if (gw >= BB) return;
    float4 hv = *(const float4*)&g_h[(size_t)gw * HH + lane * 4];
    *(float4*)&out_emb[(size_t)gw * HH + lane * 4] = hv;
    float ss = hv.x * hv.x + hv.y * hv.y + hv.z * hv.z + hv.w * hv.w;
    ss = warp_sum(ss);
    float inv = 1.f / fmaxf(sqrtf(ss), 1e-8f);
    unsigned h0, l0, h1, l1;
    split2(hv.x * inv, hv.y * inv, h0, l0);
    split2(hv.z * inv, hv.w * inv, h1, l1);
    unsigned* ph = (unsigned*)&g_an_hi[(size_t)gw * HH + lane * 4];
    unsigned* pl = (unsigned*)&g_an_lo[(size_t)gw * HH + lane * 4];
    ph[0] = h0; ph[1] = h1;
    pl[0] = l0; pl[1] = l1;
}

// ------------------------- sim + top-5 (mma, A resident, 7-way col split) ----------------
__global__ __launch_bounds__(256) void simtopk_mma_kernel() {
    extern __shared__ __align__(16) unsigned char S[];
    const int SZ = 128 * RS_S * 4;    // 34816 B
    unsigned* Ah32 = (unsigned*)S;
    unsigned* Al32 = (unsigned*)(S + SZ);
    unsigned* Bh32 = (unsigned*)(S + 2 * SZ);
    unsigned* Bl32 = (unsigned*)(S + 3 * SZ);
    uint4* Ah4 = (uint4*)Ah32;
    uint4* Al4 = (uint4*)Al32;
    uint4* Bh4 = (uint4*)Bh32;
    uint4* Bl4 = (uint4*)Bl32;
    int tid = threadIdx.x;
    int wid = tid >> 5, lane = tid & 31;
    int wm = wid & 3, wn = wid >> 2;
    int g = lane >> 2, tg = lane & 3;
    int row0 = blockIdx.x * 128;
    int tstart = blockIdx.y * TPB_Y;
    int tend = min(NTL, tstart + TPB_Y);

    // Stage A (rows of this block) ONCE: 128 rows x 128 k, hi+lo
    #pragma unroll
    for (int t = 0; t < 8; t++) {
        int idx = tid + t * 256;     // 0..2047
        int r = idx >> 4, j = idx & 15;
        int grow = row0 + r;
        uint4 vh = make_uint4(0, 0, 0, 0), vl = vh;
        if (grow < BB) {
            vh = ((const uint4*)(g_an_hi + (size_t)grow * HH))[j];
            vl = ((const uint4*)(g_an_lo + (size_t)grow * HH))[j];
        }
        Ah4[r * 17 + j] = vh;
        Al4[r * 17 + j] = vl;
    }

    float tv[2][2][KK];
    int   ti[2][2][KK];
    #pragma unroll
    for (int a = 0; a < 2; a++)
        #pragma unroll
        for (int b = 0; b < 2; b++)
            #pragma unroll
            for (int s = 0; s < KK; s++) { tv[a][b][s] = -1e30f; ti[a][b][s] = -1; }

    for (int ct = tstart; ct < tend; ct++) {
        int col0 = ct * 128;
        // Load B tile (128 cols x 128 k hi/lo)
        #pragma unroll
        for (int t = 0; t < 8; t++) {
            int idx = tid + t * 256;
            int r = idx >> 4, j = idx & 15;
            int n = col0 + r;
            uint4 vh = make_uint4(0, 0, 0, 0), vl = vh;
            if (n < BB) {
                vh = ((const uint4*)(g_an_hi + (size_t)n * HH))[j];
                vl = ((const uint4*)(g_an_lo + (size_t)n * HH))[j];
            }
            Bh4[r * 17 + j] = vh;
            Bl4[r * 17 + j] = vl;
        }
        __syncthreads();

        float acc[2][8][4];
        #pragma unroll
        for (int a = 0; a < 2; a++)
            #pragma unroll
            for (int b = 0; b < 8; b++)
                #pragma unroll
                for (int c = 0; c < 4; c++) acc[a][b][c] = 0.f;

        mma_chunk<RS_S, 8>(Ah32, Al32, Bh32, Bl32, wm, wn, g, tg, acc);
        __syncthreads();   // before next tile overwrites B

        #pragma unroll
        for (int mf = 0; mf < 2; mf++) {
            #pragma unroll
            for (int nf = 0; nf < 8; nf++) {
                int c0 = col0 + wn * 64 + nf * 8 + tg * 2;
                if (c0 < BB)     { topk_insert(tv[mf][0], ti[mf][0], acc[mf][nf][0], c0);
                                   topk_insert(tv[mf][1], ti[mf][1], acc[mf][nf][2], c0); }
                if (c0 + 1 < BB) { topk_insert(tv[mf][0], ti[mf][0], acc[mf][nf][1], c0 + 1);
                                   topk_insert(tv[mf][1], ti[mf][1], acc[mf][nf][3], c0 + 1); }
            }
        }
    }

    // Stage 1: shuffle-merge across the 4 tg lanes (same rows, different col subsets)
    #pragma unroll
    for (int off = 2; off >= 1; off >>= 1) {
        #pragma unroll
        for (int mf = 0; mf < 2; mf++)
            #pragma unroll
            for (int h = 0; h < 2; h++) {
                float ov[KK]; int oi[KK];
                #pragma unroll
                for (int s = 0; s < KK; s++) {
                    ov[s] = __shfl_down_sync(0xffffffffu, tv[mf][h][s], off);
                    oi[s] = __shfl_down_sync(0xffffffffu, ti[mf][h][s], off);
                }
                if (tg < off) {
                    #pragma unroll
                    for (int s = 0; s < KK; s++) topk_insert(tv[mf][h], ti[mf][h], ov[s], oi[s]);
                }
            }
    }

    // Stage 2: 2 partials per row (one per wn) via smem [128][10]
    __syncthreads();
    float* mv = (float*)S;                  // 5120 B
    int*   mi = (int*)(S + 5120);           // 5120 B
    if (tg == 0) {
        #pragma unroll
        for (int mf = 0; mf < 2; mf++)
            #pragma unroll
            for (int h = 0; h < 2; h++) {
                int rb = wm * 32 + mf * 16 + h * 8 + g;
                #pragma unroll
                for (int s = 0; s < KK; s++) {
                    mv[rb * 10 + wn * KK + s] = tv[mf][h][s];
                    mi[rb * 10 + wn * KK + s] = ti[mf][h][s];
                }
            }
    }
    __syncthreads();
    if (tid < 128) {
        int grow = row0 + tid;
        if (grow < BB) {
            float bv[KK]; int bi[KK];
            #pragma unroll
            for (int s = 0; s < KK; s++) { bv[s] = -1e30f; bi[s] = -1; }
            #pragma unroll
            for (int s = 0; s < 10; s++)
                topk_insert(bv, bi, mv[tid * 10 + s], mi[tid * 10 + s]);
            #pragma unroll
            for (int s = 0; s < KK; s++) {
                g_topvP[grow * NPART + blockIdx.y * KK + s] = bv[s];
                g_topiP[grow * NPART + blockIdx.y * KK + s] = bi[s];
            }
        }
    }
}

// ------------------------- final = eta*p_lc + (1-eta)*log_softmax(fused) -------------------
__global__ __launch_bounds__(128) void final_kernel(const int* __restrict__ y,
                                                    float* __restrict__ out_final) {
    int gw = (blockIdx.x * blockDim.x + threadIdx.x) >> 5;
    int lane = threadIdx.x & 31;
    if (gw >= BB) return;
    float bv[KK]; int bi[KK];
    #pragma unroll
    for (int s = 0; s < KK; s++) { bv[s] = -1e30f; bi[s] = -1; }
    #pragma unroll
    for (int s = 0; s < NPART; s++)
        topk_insert(bv, bi, g_topvP[gw * NPART + s], g_topiP[gw * NPART + s]);
    float w[KK]; int yk[KK];
    #pragma unroll
    for (int s = 0; s < KK; s++) {
        w[s] = expf(bv[s]);
        int id = bi[s];
        if (id < 0) id = 0;          // defensive
        if (id >= BB) id = BB - 1;
        yk[s] = y[id];
    }
    int c1 = lane, c2 = lane + 32;
    float f1 = 0.f, f2 = 0.f;
    #pragma unroll
    for (int s = 0; s < KK; s++) {
        if (yk[s] == c1) f1 += w[s];
        if (yk[s] == c2) f2 += w[s];
    }
    float m = f1;
    if (lane < 8) m = fmaxf(m, f2);
    m = warp_max(m);
    float se = expf(f1 - m) + ((lane < 8) ? expf(f2 - m) : 0.f);
    se = warp_sum(se);
    float lse = m + logf(se);
    float ps1 = f1 - lse;
    out_final[gw * CC + c1] = ETA * g_plc[gw * CC + c1] + (1.f - ETA) * ps1;
    if (lane < 8) {
        float ps2 = f2 - lse;
        out_final[gw * CC + c2] = ETA * g_plc[gw * CC + c2] + (1.f - ETA) * ps2;
    }
}

// ------------------------- launch -------------------------
extern "C" void kernel_launch(void* const* d_in, const int* in_sizes, int n_in,
                              void* d_out, int out_size) {
    const float* x  = (const float*)d_in[0];
    const int*   ei = (const int*)d_in[1];
    const float* ew = (const float*)d_in[2];
    const int*   y  = (const int*)d_in[3];
    int o = (n_in >= 11) ? 5 : 4;
    const float* W1 = (const float*)d_in[o + 0];
    const float* b1 = (const float*)d_in[o + 1];
    const float* cw1 = (const float*)d_in[o + 2];
    const float* cw2 = (const float*)d_in[o + 3];
    const float* W2 = (const float*)d_in[o + 4];
    const float* b2 = (const float*)d_in[o + 5];
    float* out = (float*)d_out;
    float* out_final = out;
    float* out_emb = out + BB * CC;

    const int SMEM_L = 4 * 128 * RS_L * 4;   // 73728
    const int SMEM_S = 4 * 128 * RS_S * 4;   // 139264
    static int attr_done = 0;
    if (!attr_done) {
        cudaFuncSetAttribute(input_mma_kernel, cudaFuncAttributeMaxDynamicSharedMemorySize, SMEM_L);
        cudaFuncSetAttribute(layer_mma_kernel, cudaFuncAttributeMaxDynamicSharedMemorySize, SMEM_L);
        cudaFuncSetAttribute(simtopk_mma_kernel, cudaFuncAttributeMaxDynamicSharedMemorySize, SMEM_S);
        attr_done = 1;
    }

    // weight prep
    prep_input_w_kernel<<<(HH * 512 + 255) / 256, 256>>>(W1);
    prep_layer_w_kernel<<<(LL * HH * HH + 255) / 256, 256>>>(cw1, cw2);

    // CSR build
    zero_counts_kernel<<<(NN + 255) / 256, 256>>>();
    hist_kernel<<<(EE + 255) / 256, 256>>>(ei);
    scan_kernel<<<1, 1024>>>();
    csr_fill_kernel<<<(EE + 255) / 256, 256>>>(ei, ew);

    // input GEMM
    input_mma_kernel<<<(NN + 127) / 128, 256, SMEM_L>>>(x, b1);

    // layers
    for (int l = 0; l < LL; l++) {
        spmm_kernel<<<(NN * 32 + 255) / 256, 256>>>();
        layer_mma_kernel<<<(NN + 127) / 128, 256, SMEM_L>>>(l);
    }

    // heads
    plc_kernel<<<(BB * 32 + 127) / 128, 128>>>(W2, b2);
    normalize_kernel<<<(BB * 32 + 127) / 128, 128>>>(out_emb);
    simtopk_mma_kernel<<<dim3(NTL, YS), 256, SMEM_S>>>();
    final_kernel<<<(BB * 32 + 127) / 128, 128>>>(y, out_final);
}

// round 6
// speedup vs baseline: 1.9582x; 1.0548x over previous
#include <cuda_runtime.h>
#include <cuda_bf16.h>
#include <math.h>

#define NN   50000
#define EE   800000
#define DIN_ 500
#define HH   128
#define CC   40
#define BB   10000
#define LL   9
#define KK   5
#define ALPHA 0.5f
#define ETA   0.5f

#define RS_L 36          // smem row stride in words for 64-k chunks (32 words + 4 pad)
#define RS_S 68          // smem row stride in words for 128-k tiles (64 words + 4 pad)
#define NTL  79          // ceil(BB/128)
#define YS   7           // y-splits in simtopk
#define TPB_Y 12         // column tiles per y-split (7*12 >= 79)
#define NPART (YS * KK)  // 35 partial slots per row

// ------------------------- scratch (device globals) -------------------------
__device__ float g_h[NN * HH];
__device__ __nv_bfloat16 g_p_hi[NN * HH], g_p_lo[NN * HH];
__device__ __nv_bfloat16 g_x0_hi[NN * HH], g_x0_lo[NN * HH];
__device__ __nv_bfloat16 g_an_hi[BB * HH], g_an_lo[BB * HH];
__device__ __nv_bfloat16 g_w1t_hi[HH * 512], g_w1t_lo[HH * 512];
__device__ __nv_bfloat16 g_wl1_hi[LL * HH * HH], g_wl1_lo[LL * HH * HH];
__device__ __nv_bfloat16 g_wl2_hi[LL * HH * HH], g_wl2_lo[LL * HH * HH];
__device__ int   g_cnt[NN];
__device__ int   g_fill[NN];
__device__ int   g_rowptr[NN + 1];
__device__ int   g_colidx[EE];
__device__ float g_wsorted[EE];
__device__ float g_plc[BB * CC];
__device__ float g_topvP[BB * NPART];
__device__ int   g_topiP[BB * NPART];

// ------------------------- helpers -------------------------
__device__ __forceinline__ float warp_max(float v) {
    #pragma unroll
    for (int o = 16; o > 0; o >>= 1) v = fmaxf(v, __shfl_xor_sync(0xffffffffu, v, o));
    return v;
}
__device__ __forceinline__ float warp_sum(float v) {
    #pragma unroll
    for (int o = 16; o > 0; o >>= 1) v += __shfl_xor_sync(0xffffffffu, v, o);
    return v;
}
__device__ __forceinline__ void split2(float a, float b, unsigned& hi, unsigned& lo) {
    __nv_bfloat16 ha = __float2bfloat16(a);
    __nv_bfloat16 hb = __float2bfloat16(b);
    float ra = a - __bfloat162float(ha);
    float rb = b - __bfloat162float(hb);
    __nv_bfloat16 la = __float2bfloat16(ra);
    __nv_bfloat16 lb = __float2bfloat16(rb);
    hi = (unsigned)(*(unsigned short*)&ha) | ((unsigned)(*(unsigned short*)&hb) << 16);
    lo = (unsigned)(*(unsigned short*)&la) | ((unsigned)(*(unsigned short*)&lb) << 16);
}

// top-5 insertion, sorted descending; ties -> lower index first
__device__ __forceinline__ void topk_insert(float (&tv)[KK], int (&ti)[KK], float v, int c) {
    if (v > tv[KK - 1] || (v == tv[KK - 1] && c < ti[KK - 1])) {
        tv[KK - 1] = v; ti[KK - 1] = c;
        #pragma unroll
        for (int p = KK - 1; p > 0; p--) {
            bool sw = (tv[p] > tv[p - 1]) || (tv[p] == tv[p - 1] && ti[p] < ti[p - 1]);
            if (sw) {
                float fv = tv[p]; tv[p] = tv[p - 1]; tv[p - 1] = fv;
                int fi = ti[p]; ti[p] = ti[p - 1]; ti[p - 1] = fi;
            }
        }
    }
}

__device__ __forceinline__ void mma_bf16(float d[4], const unsigned a[4], const unsigned b[2]) {
    asm volatile(
        "mma.sync.aligned.m16n8k16.row.col.f32.bf16.bf16.f32 "
        "{%0,%1,%2,%3}, {%4,%5,%6,%7}, {%8,%9}, {%0,%1,%2,%3};\n"
        : "+f"(d[0]), "+f"(d[1]), "+f"(d[2]), "+f"(d[3])
        : "r"(a[0]), "r"(a[1]), "r"(a[2]), "r"(a[3]), "r"(b[0]), "r"(b[1]));
}

__device__ __forceinline__ void ldsm4(unsigned r[4], unsigned addr) {
    asm volatile("ldmatrix.sync.aligned.m8n8.x4.shared.b16 {%0,%1,%2,%3}, [%4];"
        : "=r"(r[0]), "=r"(r[1]), "=r"(r[2]), "=r"(r[3]) : "r"(addr));
}

// warp 32x64 tile; NK k16-steps from staged (hi,lo) tiles with row stride RS words.
// Fragment loads via ldmatrix (A: per-mf x4; B: per 16-col pair x4).
template<int RS, int NK>
__device__ __forceinline__ void mma_chunk(unsigned sAh, unsigned sAl, unsigned sBh, unsigned sBl,
                                          int wm, int wn, int lane, float acc[2][8][4]) {
    // A x4: lanes 0-7 -> M0 rows (A rows 0-7, words ko..ko+3); 8-15 -> rows 8-15 same words;
    //       16-23 -> rows 0-7, words ko+4..7; 24-31 -> rows 8-15, words ko+4..7
    int a_row = (lane & 7) | (((lane >> 3) & 1) << 3);
    int a_w   = (lane >> 4) << 2;
    // B x4 (two 8-col groups): lanes 0-7 -> group0 rows, words ko; 8-15 -> group0, words ko+4;
    //       16-23 -> group1 rows, words ko; 24-31 -> group1, words ko+4
    int b_row = (lane & 7) + ((lane >> 4) << 3);
    int b_w   = ((lane >> 3) & 1) << 2;
    #pragma unroll
    for (int ks = 0; ks < NK; ks++) {
        int ko = ks * 8;
        unsigned ah[2][4], al[2][4];
        #pragma unroll
        for (int mf = 0; mf < 2; mf++) {
            unsigned off = (unsigned)(((wm * 32 + mf * 16 + a_row) * RS + ko + a_w) * 4);
            ldsm4(ah[mf], sAh + off);
            ldsm4(al[mf], sAl + off);
        }
        #pragma unroll
        for (int p = 0; p < 4; p++) {
            unsigned bh[4], bl[4];
            unsigned off = (unsigned)(((wn * 64 + p * 16 + b_row) * RS + ko + b_w) * 4);
            ldsm4(bh, sBh + off);
            ldsm4(bl, sBl + off);
            #pragma unroll
            for (int q = 0; q < 2; q++) {
                int nf = p * 2 + q;
                unsigned bhq[2] = {bh[q * 2], bh[q * 2 + 1]};
                unsigned blq[2] = {bl[q * 2], bl[q * 2 + 1]};
                #pragma unroll
                for (int mf = 0; mf < 2; mf++) {
                    mma_bf16(acc[mf][nf], ah[mf], bhq);
                    mma_bf16(acc[mf][nf], ah[mf], blq);
                    mma_bf16(acc[mf][nf], al[mf], bhq);
                }
            }
        }
    }
}

// ------------------------- weight prep -------------------------
__global__ void prep_input_w_kernel(const float* __restrict__ W1) {
    int idx = blockIdx.x * blockDim.x + threadIdx.x;
    if (idx >= HH * 512) return;
    int n = idx >> 9, k = idx & 511;
    float v = (k < DIN_) ? W1[k * HH + n] : 0.f;
    __nv_bfloat16 hi = __float2bfloat16(v);
    __nv_bfloat16 lo = __float2bfloat16(v - __bfloat162float(hi));
    g_w1t_hi[idx] = hi; g_w1t_lo[idx] = lo;
}

__global__ void prep_layer_w_kernel(const float* __restrict__ cw1, const float* __restrict__ cw2) {
    int idx = blockIdx.x * blockDim.x + threadIdx.x;
    if (idx >= LL * HH * HH) return;
    int l = idx / (HH * HH);
    int r = idx % (HH * HH);
    int n = r >> 7, k = r & 127;
    float beta = logf(1.f / (float)(l + 1) + 1.f);
    float diag = (n == k) ? (1.f - beta) : 0.f;
    float v1 = beta * cw1[l * HH * HH + k * HH + n] + diag;
    float v2 = beta * cw2[l * HH * HH + k * HH + n] + diag;
    __nv_bfloat16 h1 = __float2bfloat16(v1);
    g_wl1_hi[idx] = h1; g_wl1_lo[idx] = __float2bfloat16(v1 - __bfloat162float(h1));
    __nv_bfloat16 h2 = __float2bfloat16(v2);
    g_wl2_hi[idx] = h2; g_wl2_lo[idx] = __float2bfloat16(v2 - __bfloat162float(h2));
}

// ------------------------- CSR build -------------------------
__global__ void zero_counts_kernel() {
    int i = blockIdx.x * blockDim.x + threadIdx.x;
    if (i < NN) { g_cnt[i] = 0; g_fill[i] = 0; }
}
__global__ void hist_kernel(const int* __restrict__ ei) {
    int e = blockIdx.x * blockDim.x + threadIdx.x;
    if (e < EE) atomicAdd(&g_cnt[ei[e]], 1);
}
__global__ void scan_kernel() {
    __shared__ int sh[1024];
    int carry = 0;
    if (threadIdx.x == 0) g_rowptr[0] = 0;
    for (int base = 0; base < NN; base += 1024) {
        int i = base + threadIdx.x;
        int v = (i < NN) ? g_cnt[i] : 0;
        sh[threadIdx.x] = v;
        __syncthreads();
        #pragma unroll
        for (int off = 1; off < 1024; off <<= 1) {
            int t = 0;
            if (threadIdx.x >= off) t = sh[threadIdx.x - off];
            __syncthreads();
            sh[threadIdx.x] += t;
            __syncthreads();
        }
        if (i < NN) g_rowptr[i + 1] = carry + sh[threadIdx.x];
        carry += sh[1023];
        __syncthreads();
    }
}
__global__ void csr_fill_kernel(const int* __restrict__ ei, const float* __restrict__ ew) {
    int e = blockIdx.x * blockDim.x + threadIdx.x;
    if (e < EE) {
        int r = ei[e];
        int pos = g_rowptr[r] + atomicAdd(&g_fill[r], 1);
        g_colidx[pos] = ei[EE + e];
        g_wsorted[pos] = ew[e];
    }
}

// ------------------------- input GEMM (mma): h = relu(x@W1 + b1); x0s = alpha*h ----------
__global__ __launch_bounds__(256) void input_mma_kernel(const float* __restrict__ x,
                                                        const float* __restrict__ b1) {
    extern __shared__ __align__(16) unsigned char S[];
    const int SZ = 128 * RS_L * 4;    // 18432 B per array
    unsigned* Ah32 = (unsigned*)S;
    unsigned* Al32 = (unsigned*)(S + SZ);
    uint4* Bh4 = (uint4*)(S + 2 * SZ);
    uint4* Bl4 = (uint4*)(S + 3 * SZ);
    unsigned sAh = (unsigned)__cvta_generic_to_shared(S);
    unsigned sAl = sAh + SZ, sBh = sAh + 2 * SZ, sBl = sAh + 3 * SZ;
    int tid = threadIdx.x;
    int wid = tid >> 5, lane = tid & 31;
    int wm = wid & 3, wn = wid >> 2;
    int g = lane >> 2, tg = lane & 3;
    int row0 = blockIdx.x * 128;

    float acc[2][8][4];
    #pragma unroll
    for (int a = 0; a < 2; a++)
        #pragma unroll
        for (int b = 0; b < 8; b++)
            #pragma unroll
            for (int c = 0; c < 4; c++) acc[a][b][c] = 0.f;

    for (int c = 0; c < 8; c++) {
        int k0 = c * 64;
        #pragma unroll
        for (int t = 0; t < 8; t++) {
            int idx = tid + t * 256;     // 0..2047
            int r = idx >> 4, q = idx & 15;
            int grow = row0 + r;
            int kk = k0 + q * 4;
            float4 f = make_float4(0.f, 0.f, 0.f, 0.f);
            if (grow < NN && kk < DIN_)
                f = *(const float4*)&x[(size_t)grow * DIN_ + kk];
            unsigned h0, l0, h1, l1;
            split2(f.x, f.y, h0, l0);
            split2(f.z, f.w, h1, l1);
            int w = r * RS_L + q * 2;
            Ah32[w] = h0; Ah32[w + 1] = h1;
            Al32[w] = l0; Al32[w + 1] = l1;
        }
        #pragma unroll
        for (int t = 0; t < 4; t++) {
            int idx = tid + t * 256;     // 0..1023
            int n = idx >> 3, j = idx & 7;
            Bh4[n * 9 + j] = ((const uint4*)(g_w1t_hi + n * 512 + k0))[j];
            Bl4[n * 9 + j] = ((const uint4*)(g_w1t_lo + n * 512 + k0))[j];
        }
        __syncthreads();
        mma_chunk<RS_L, 4>(sAh, sAl, sBh, sBl, wm, wn, lane, acc);
        __syncthreads();
    }

    #pragma unroll
    for (int mf = 0; mf < 2; mf++) {
        #pragma unroll
        for (int nf = 0; nf < 8; nf++) {
            int col = wn * 64 + nf * 8 + tg * 2;
            float2 bias = *(const float2*)&b1[col];
            #pragma unroll
            for (int h = 0; h < 2; h++) {
                int row = row0 + wm * 32 + mf * 16 + h * 8 + g;
                if (row < NN) {
                    float v0 = fmaxf(acc[mf][nf][h * 2 + 0] + bias.x, 0.f);
                    float v1 = fmaxf(acc[mf][nf][h * 2 + 1] + bias.y, 0.f);
                    *(float2*)&g_h[(size_t)row * HH + col] = make_float2(v0, v1);
                    unsigned hi, lo;
                    split2(ALPHA * v0, ALPHA * v1, hi, lo);
                    *(unsigned*)&g_x0_hi[(size_t)row * HH + col] = hi;
                    *(unsigned*)&g_x0_lo[(size_t)row * HH + col] = lo;
                }
            }
        }
    }
}

// ------------------------- SpMM: p = (1-alpha)*A@h -> bf16 hi/lo -------------------------
__global__ __launch_bounds__(256) void spmm_kernel() {
    int gt = blockIdx.x * blockDim.x + threadIdx.x;
    int row = gt >> 5;
    int lane = gt & 31;
    if (row >= NN) return;
    int s = g_rowptr[row], e = g_rowptr[row + 1];
    float4 acc = make_float4(0.f, 0.f, 0.f, 0.f);
    int i = s;
    for (; i + 4 <= e; i += 4) {
        int c0 = g_colidx[i],     c1 = g_colidx[i + 1];
        int c2 = g_colidx[i + 2], c3 = g_colidx[i + 3];
        float w0 = g_wsorted[i],     w1 = g_wsorted[i + 1];
        float w2 = g_wsorted[i + 2], w3 = g_wsorted[i + 3];
        float4 h0 = *(const float4*)&g_h[(size_t)c0 * HH + lane * 4];
        float4 h1 = *(const float4*)&g_h[(size_t)c1 * HH + lane * 4];
        float4 h2 = *(const float4*)&g_h[(size_t)c2 * HH + lane * 4];
        float4 h3 = *(const float4*)&g_h[(size_t)c3 * HH + lane * 4];
        acc.x += w0 * h0.x + w1 * h1.x + w2 * h2.x + w3 * h3.x;
        acc.y += w0 * h0.y + w1 * h1.y + w2 * h2.y + w3 * h3.y;
        acc.z += w0 * h0.z + w1 * h1.z + w2 * h2.z + w3 * h3.z;
        acc.w += w0 * h0.w + w1 * h1.w + w2 * h2.w + w3 * h3.w;
    }
    for (; i < e; i++) {
        int c = g_colidx[i];
        float w = g_wsorted[i];
        float4 hv = *(const float4*)&g_h[(size_t)c * HH + lane * 4];
        acc.x += w * hv.x; acc.y += w * hv.y;
        acc.z += w * hv.z; acc.w += w * hv.w;
    }
    const float s1 = 1.f - ALPHA;
    acc.x *= s1; acc.y *= s1; acc.z *= s1; acc.w *= s1;
    unsigned h0, l0, h1, l1;
    split2(acc.x, acc.y, h0, l0);
    split2(acc.z, acc.w, h1, l1);
    unsigned* ph = (unsigned*)&g_p_hi[(size_t)row * HH + lane * 4];
    unsigned* pl = (unsigned*)&g_p_lo[(size_t)row * HH + lane * 4];
    ph[0] = h0; ph[1] = h1;
    pl[0] = l0; pl[1] = l1;
}

// ------------------------- layer GEMM (mma): h = relu(h + p@W1' + x0s@W2') ---------------
__global__ __launch_bounds__(256) void layer_mma_kernel(int l) {
    extern __shared__ __align__(16) unsigned char S[];
    const int SZ = 128 * RS_L * 4;
    uint4* Ah4 = (uint4*)S;
    uint4* Al4 = (uint4*)(S + SZ);
    uint4* Bh4 = (uint4*)(S + 2 * SZ);
    uint4* Bl4 = (uint4*)(S + 3 * SZ);
    unsigned sAh = (unsigned)__cvta_generic_to_shared(S);
    unsigned sAl = sAh + SZ, sBh = sAh + 2 * SZ, sBl = sAh + 3 * SZ;
    int tid = threadIdx.x;
    int wid = tid >> 5, lane = tid & 31;
    int wm = wid & 3, wn = wid >> 2;
    int g = lane >> 2, tg = lane & 3;
    int row0 = blockIdx.x * 128;
    const size_t wbase = (size_t)l * HH * HH;

    float acc[2][8][4];
    #pragma unroll
    for (int a = 0; a < 2; a++)
        #pragma unroll
        for (int b = 0; b < 8; b++)
            #pragma unroll
            for (int c = 0; c < 4; c++) acc[a][b][c] = 0.f;

    #pragma unroll
    for (int c = 0; c < 4; c++) {
        int koff = (c & 1) * 64;
        const __nv_bfloat16 *ah_src, *al_src, *bh_src, *bl_src;
        if (c < 2) { ah_src = g_p_hi;  al_src = g_p_lo;
                     bh_src = g_wl1_hi + wbase; bl_src = g_wl1_lo + wbase; }
        else       { ah_src = g_x0_hi; al_src = g_x0_lo;
                     bh_src = g_wl2_hi + wbase; bl_src = g_wl2_lo + wbase; }
        #pragma unroll
        for (int t = 0; t < 4; t++) {
            int idx = tid + t * 256;     // 0..1023
            int r = idx >> 3, j = idx & 7;
            int grow = row0 + r;
            uint4 vh = make_uint4(0, 0, 0, 0), vl = vh;
            if (grow < NN) {
                vh = ((const uint4*)(ah_src + (size_t)grow * HH + koff))[j];
                vl = ((const uint4*)(al_src + (size_t)grow * HH + koff))[j];
            }
            Ah4[r * 9 + j] = vh; Al4[r * 9 + j] = vl;
            Bh4[r * 9 + j] = ((const uint4*)(bh_src + r * HH + koff))[j];
            Bl4[r * 9 + j] = ((const uint4*)(bl_src + r * HH + koff))[j];
        }
        __syncthreads();
        mma_chunk<RS_L, 4>(sAh, sAl, sBh, sBl, wm, wn, lane, acc);
        __syncthreads();
    }

    #pragma unroll
    for (int mf = 0; mf < 2; mf++) {
        #pragma unroll
        for (int nf = 0; nf < 8; nf++) {
            int col = wn * 64 + nf * 8 + tg * 2;
            #pragma unroll
            for (int h = 0; h < 2; h++) {
                int row = row0 + wm * 32 + mf * 16 + h * 8 + g;
                if (row < NN) {
                    float2* hp = (float2*)&g_h[(size_t)row * HH + col];
                    float2 hv = *hp;
                    hv.x = fmaxf(hv.x + acc[mf][nf][h * 2 + 0], 0.f);
                    hv.y = fmaxf(hv.y + acc[mf][nf][h * 2 + 1], 0.f);
                    *hp = hv;
                }
            }
        }
    }
}

// ------------------------- p_lc = log_softmax(h[:B] @ W2 + b2) -------------------------
__global__ __launch_bounds__(128) void plc_kernel(const float* __restrict__ W2,
                                                  const float* __restrict__ b2) {
    __shared__ float hrow[4][HH];
    int gw = (blockIdx.x * blockDim.x + threadIdx.x) >> 5;
    int lane = threadIdx.x & 31;
    int wl = threadIdx.x >> 5;
    if (gw >= BB) return;
    float4 hv = *(const float4*)&g_h[(size_t)gw * HH + lane * 4];
    *(float4*)&hrow[wl][lane * 4] = hv;
    __syncwarp();
    float acc1 = 0.f, acc2 = 0.f;
    int c2 = lane + 32;
    for (int k = 0; k < HH; k++) {
        float h = hrow[wl][k];
        acc1 += h * W2[k * CC + lane];
        if (lane < 8) acc2 += h * W2[k * CC + c2];
    }
    acc1 += b2[lane];
    if (lane < 8) acc2 += b2[c2];
    float m = acc1;
    if (lane < 8) m = fmaxf(m, acc2);
    m = warp_max(m);
    float se = expf(acc1 - m) + ((lane < 8) ? expf(acc2 - m) : 0.f);
    se = warp_sum(se);
    float lse = m + logf(se);
    g_plc[gw * CC + lane] = acc1 - lse;
    if (lane < 8) g_plc[gw * CC + c2] = acc2 - lse;
}

// ------------------------- emb out + an split -------------------------
__global__ __launch_bounds__(128) void normalize_kernel(float* __restrict__ out_emb) {
    int gw = (blockIdx.x * blockDim.x + threadIdx.x) >> 5;
    int lane = threadIdx.x & 31;
    if (gw >= BB) return;
    float4 hv = *(const float4*)&g_h[(size_t)gw * HH + lane * 4];
    *(float4*)&out_emb[(size_t)gw * HH + lane * 4] = hv;
    float ss = hv.x * hv.x + hv.y * hv.y + hv.z * hv.z + hv.w * hv.w;
    ss = warp_sum(ss);
    float inv = 1.f / fmaxf(sqrtf(ss), 1e-8f);
    unsigned h0, l0, h1, l1;
    split2(hv.x * inv, hv.y * inv, h0, l0);
    split2(hv.z * inv, hv.w * inv, h1, l1);
    unsigned* ph = (unsigned*)&g_an_hi[(size_t)gw * HH + lane * 4];
    unsigned* pl = (unsigned*)&g_an_lo[(size_t)gw * HH + lane * 4];
    ph[0] = h0; ph[1] = h1;
    pl[0] = l0; pl[1] = l1;
}

// ------------------------- sim + top-5 (mma, A resident, 7-way col split) ----------------
__global__ __launch_bounds__(256) void simtopk_mma_kernel() {
    extern __shared__ __align__(16) unsigned char S[];
    const int SZ = 128 * RS_S * 4;    // 34816 B
    uint4* Ah4 = (uint4*)S;
    uint4* Al4 = (uint4*)(S + SZ);
    uint4* Bh4 = (uint4*)(S + 2 * SZ);
    uint4* Bl4 = (uint4*)(S + 3 * SZ);
    unsigned sAh = (unsigned)__cvta_generic_to_shared(S);
    unsigned sAl = sAh + SZ, sBh = sAh + 2 * SZ, sBl = sAh + 3 * SZ;
    int tid = threadIdx.x;
    int wid = tid >> 5, lane = tid & 31;
    int wm = wid & 3, wn = wid >> 2;
    int g = lane >> 2, tg = lane & 3;
    int row0 = blockIdx.x * 128;
    int tstart = blockIdx.y * TPB_Y;
    int tend = min(NTL, tstart + TPB_Y);

    // Stage A (rows of this block) ONCE: 128 rows x 128 k, hi+lo
    #pragma unroll
    for (int t = 0; t < 8; t++) {
        int idx = tid + t * 256;     // 0..2047
        int r = idx >> 4, j = idx & 15;
        int grow = row0 + r;
        uint4 vh = make_uint4(0, 0, 0, 0), vl = vh;
        if (grow < BB) {
            vh = ((const uint4*)(g_an_hi + (size_t)grow * HH))[j];
            vl = ((const uint4*)(g_an_lo + (size_t)grow * HH))[j];
        }
        Ah4[r * 17 + j] = vh;
        Al4[r * 17 + j] = vl;
    }

    float tv[2][2][KK];
    int   ti[2][2][KK];
    #pragma unroll
    for (int a = 0; a < 2; a++)
        #pragma unroll
        for (int b = 0; b < 2; b++)
            #pragma unroll
            for (int s = 0; s < KK; s++) { tv[a][b][s] = -1e30f; ti[a][b][s] = -1; }

    for (int ct = tstart; ct < tend; ct++) {
        int col0 = ct * 128;
        #pragma unroll
        for (int t = 0; t < 8; t++) {
            int idx = tid + t * 256;
            int r = idx >> 4, j = idx & 15;
            int n = col0 + r;
            uint4 vh = make_uint4(0, 0, 0, 0), vl = vh;
            if (n < BB) {
                vh = ((const uint4*)(g_an_hi + (size_t)n * HH))[j];
                vl = ((const uint4*)(g_an_lo + (size_t)n * HH))[j];
            }
            Bh4[r * 17 + j] = vh;
            Bl4[r * 17 + j] = vl;
        }
        __syncthreads();

        float acc[2][8][4];
        #pragma unroll
        for (int a = 0; a < 2; a++)
            #pragma unroll
            for (int b = 0; b < 8; b++)
                #pragma unroll
                for (int c = 0; c < 4; c++) acc[a][b][c] = 0.f;

        mma_chunk<RS_S, 8>(sAh, sAl, sBh, sBl, wm, wn, lane, acc);
        __syncthreads();   // before next tile overwrites B

        #pragma unroll
        for (int mf = 0; mf < 2; mf++) {
            #pragma unroll
            for (int nf = 0; nf < 8; nf++) {
                int c0 = col0 + wn * 64 + nf * 8 + tg * 2;
                if (c0 < BB)     { topk_insert(tv[mf][0], ti[mf][0], acc[mf][nf][0], c0);
                                   topk_insert(tv[mf][1], ti[mf][1], acc[mf][nf][2], c0); }
                if (c0 + 1 < BB) { topk_insert(tv[mf][0], ti[mf][0], acc[mf][nf][1], c0 + 1);
                                   topk_insert(tv[mf][1], ti[mf][1], acc[mf][nf][3], c0 + 1); }
            }
        }
    }

    // Stage 1: shuffle-merge across the 4 tg lanes
    #pragma unroll
    for (int off = 2; off >= 1; off >>= 1) {
        #pragma unroll
        for (int mf = 0; mf < 2; mf++)
            #pragma unroll
            for (int h = 0; h < 2; h++) {
                float ov[KK]; int oi[KK];
                #pragma unroll
                for (int s = 0; s < KK; s++) {
                    ov[s] = __shfl_down_sync(0xffffffffu, tv[mf][h][s], off);
                    oi[s] = __shfl_down_sync(0xffffffffu, ti[mf][h][s], off);
                }
                if (tg < off) {
                    #pragma unroll
                    for (int s = 0; s < KK; s++) topk_insert(tv[mf][h], ti[mf][h], ov[s], oi[s]);
                }
            }
    }

    // Stage 2: 2 partials per row (one per wn) via smem [128][10]
    __syncthreads();
    float* mv = (float*)S;                  // 5120 B
    int*   mi = (int*)(S + 5120);           // 5120 B
    if (tg == 0) {
        #pragma unroll
        for (int mf = 0; mf < 2; mf++)
            #pragma unroll
            for (int h = 0; h < 2; h++) {
                int rb = wm * 32 + mf * 16 + h * 8 + g;
                #pragma unroll
                for (int s = 0; s < KK; s++) {
                    mv[rb * 10 + wn * KK + s] = tv[mf][h][s];
                    mi[rb * 10 + wn * KK + s] = ti[mf][h][s];
                }
            }
    }
    __syncthreads();
    if (tid < 128) {
        int grow = row0 + tid;
        if (grow < BB) {
            float bv[KK]; int bi[KK];
            #pragma unroll
            for (int s = 0; s < KK; s++) { bv[s] = -1e30f; bi[s] = -1; }
            #pragma unroll
            for (int s = 0; s < 10; s++)
                topk_insert(bv, bi, mv[tid * 10 + s], mi[tid * 10 + s]);
            #pragma unroll
            for (int s = 0; s < KK; s++) {
                g_topvP[grow * NPART + blockIdx.y * KK + s] = bv[s];
                g_topiP[grow * NPART + blockIdx.y * KK + s] = bi[s];
            }
        }
    }
}

// ------------------------- final = eta*p_lc + (1-eta)*log_softmax(fused) -------------------
__global__ __launch_bounds__(128) void final_kernel(const int* __restrict__ y,
                                                    float* __restrict__ out_final) {
    int gw = (blockIdx.x * blockDim.x + threadIdx.x) >> 5;
    int lane = threadIdx.x & 31;
    if (gw >= BB) return;
    float bv[KK]; int bi[KK];
    #pragma unroll
    for (int s = 0; s < KK; s++) { bv[s] = -1e30f; bi[s] = -1; }
    #pragma unroll
    for (int s = 0; s < NPART; s++)
        topk_insert(bv, bi, g_topvP[gw * NPART + s], g_topiP[gw * NPART + s]);
    float w[KK]; int yk[KK];
    #pragma unroll
    for (int s = 0; s < KK; s++) {
        w[s] = expf(bv[s]);
        int id = bi[s];
        if (id < 0) id = 0;          // defensive
        if (id >= BB) id = BB - 1;
        yk[s] = y[id];
    }
    int c1 = lane, c2 = lane + 32;
    float f1 = 0.f, f2 = 0.f;
    #pragma unroll
    for (int s = 0; s < KK; s++) {
        if (yk[s] == c1) f1 += w[s];
        if (yk[s] == c2) f2 += w[s];
    }
    float m = f1;
    if (lane < 8) m = fmaxf(m, f2);
    m = warp_max(m);
    float se = expf(f1 - m) + ((lane < 8) ? expf(f2 - m) : 0.f);
    se = warp_sum(se);
    float lse = m + logf(se);
    float ps1 = f1 - lse;
    out_final[gw * CC + c1] = ETA * g_plc[gw * CC + c1] + (1.f - ETA) * ps1;
    if (lane < 8) {
        float ps2 = f2 - lse;
        out_final[gw * CC + c2] = ETA * g_plc[gw * CC + c2] + (1.f - ETA) * ps2;
    }
}

// ------------------------- launch -------------------------
extern "C" void kernel_launch(void* const* d_in, const int* in_sizes, int n_in,
                              void* d_out, int out_size) {
    const float* x  = (const float*)d_in[0];
    const int*   ei = (const int*)d_in[1];
    const float* ew = (const float*)d_in[2];
    const int*   y  = (const int*)d_in[3];
    int o = (n_in >= 11) ? 5 : 4;
    const float* W1 = (const float*)d_in[o + 0];
    const float* b1 = (const float*)d_in[o + 1];
    const float* cw1 = (const float*)d_in[o + 2];
    const float* cw2 = (const float*)d_in[o + 3];
    const float* W2 = (const float*)d_in[o + 4];
    const float* b2 = (const float*)d_in[o + 5];
    float* out = (float*)d_out;
    float* out_final = out;
    float* out_emb = out + BB * CC;

    const int SMEM_L = 4 * 128 * RS_L * 4;   // 73728
    const int SMEM_S = 4 * 128 * RS_S * 4;   // 139264
    static int attr_done = 0;
    if (!attr_done) {
        cudaFuncSetAttribute(input_mma_kernel, cudaFuncAttributeMaxDynamicSharedMemorySize, SMEM_L);
        cudaFuncSetAttribute(layer_mma_kernel, cudaFuncAttributeMaxDynamicSharedMemorySize, SMEM_L);
        cudaFuncSetAttribute(simtopk_mma_kernel, cudaFuncAttributeMaxDynamicSharedMemorySize, SMEM_S);
        attr_done = 1;
    }

    // weight prep
    prep_input_w_kernel<<<(HH * 512 + 255) / 256, 256>>>(W1);
    prep_layer_w_kernel<<<(LL * HH * HH + 255) / 256, 256>>>(cw1, cw2);

    // CSR build
    zero_counts_kernel<<<(NN + 255) / 256, 256>>>();
    hist_kernel<<<(EE + 255) / 256, 256>>>(ei);
    scan_kernel<<<1, 1024>>>();
    csr_fill_kernel<<<(EE + 255) / 256, 256>>>(ei, ew);

    // input GEMM
    input_mma_kernel<<<(NN + 127) / 128, 256, SMEM_L>>>(x, b1);

    // layers
    for (int l = 0; l < LL; l++) {
        spmm_kernel<<<(NN * 32 + 255) / 256, 256>>>();
        layer_mma_kernel<<<(NN + 127) / 128, 256, SMEM_L>>>(l);
    }

    // heads
    plc_kernel<<<(BB * 32 + 127) / 128, 128>>>(W2, b2);
    normalize_kernel<<<(BB * 32 + 127) / 128, 128>>>(out_emb);
    simtopk_mma_kernel<<<dim3(NTL, YS), 256, SMEM_S>>>();
    final_kernel<<<(BB * 32 + 127) / 128, 128>>>(y, out_final);
}